// round 14
// baseline (speedup 1.0000x reference)
#include <cuda_runtime.h>
#include <cuda_fp16.h>
#include <cstdint>

#define MAXB  1024
#define EMAX  (1 << 20)
#define EPS   1e-5f
#define SLOPE 0.01f

// ---------------- static device scratch (no allocations allowed) ----------------
__device__ __align__(16) float d_A [MAXB * 128];
__device__ __align__(16) float d_gx[MAXB * 64];
__device__            int   d_cnt[MAXB];
__device__ __align__(16) float d_Q [128];
__device__ __align__(16) float d_s1[128], d_t1[128], d_t2[128];
__device__ __align__(16) float d_a1[MAXB * 128], d_a2[MAXB * 128];
__device__ __align__(16) float d_S1[128], d_Q1[128], d_S2[128], d_Q2[128];
__device__ __align__(16) unsigned short d_Wt[17408]; // W^T fp16 hi [128][136]
__device__ __align__(16) int2  d_se2[EMAX];          // sorted edges {row, e_orig}
__device__            int   d_hist[MAXB], d_cur[MAXB], d_off[MAXB + 1];
__device__            int   d_bar[8];
__device__            int   d_f_e64, d_f_b64;

// ---------------- smem layout of k_edge ----------------
#define S_IDX0  0            // int4 {row,g,eorig,0} x 128
#define S_IDX1  2048
#define S_CB    4096         // 512B column buffer
#define S_OFF   4608         // 1025 ints
#define S_W     8832         // Whi [128][272B] = 34816
#define S_A     43648        // Ahi then Alo (69632); reused: dump / sum+q bufs
#define S_RAW   113280       // raw fp32 [128][132 floats] (67584)
#define SMEM_TOT 180864

// ---------------- helpers ----------------
__device__ __forceinline__ void red4(float* p, float4 v) {
    asm volatile("red.global.add.v4.f32 [%0], {%1,%2,%3,%4};"
                 :: "l"(p), "f"(v.x), "f"(v.y), "f"(v.z), "f"(v.w) : "memory");
}
__device__ __forceinline__ void redf(float* p, float v) {
    asm volatile("red.global.add.f32 [%0], %1;" :: "l"(p), "f"(v) : "memory");
}
__device__ __forceinline__ long long ldix(const void* p, long long i, int is64) {
    return is64 ? ((const long long*)p)[i] : (long long)((const int*)p)[i];
}
__device__ __forceinline__ float leaky(float z) { return z >= 0.f ? z : SLOPE * z; }
__device__ __forceinline__ uint32_t smem_u32(const void* p) {
    uint32_t a;
    asm("{ .reg .u64 t; cvta.to.shared.u64 t, %1; cvt.u32.u64 %0, t; }" : "=r"(a) : "l"(p));
    return a;
}
__device__ __forceinline__ void cpa16(uint32_t s, const void* g) {
    asm volatile("cp.async.cg.shared.global [%0], [%1], 16;" :: "r"(s), "l"(g) : "memory");
}
#define LDSM4(r, a) \
    asm volatile("ldmatrix.sync.aligned.m8n8.x4.shared.b16 {%0,%1,%2,%3}, [%4];" \
        : "=r"((r)[0]), "=r"((r)[1]), "=r"((r)[2]), "=r"((r)[3]) : "r"(a))
#define MMA16816(c, a, b0, b1) \
    asm volatile("mma.sync.aligned.m16n8k16.row.col.f32.f16.f16.f32 " \
        "{%0,%1,%2,%3}, {%4,%5,%6,%7}, {%8,%9}, {%0,%1,%2,%3};" \
        : "+f"((c)[0]), "+f"((c)[1]), "+f"((c)[2]), "+f"((c)[3]) \
        : "r"((a)[0]), "r"((a)[1]), "r"((a)[2]), "r"((a)[3]), "r"(b0), "r"(b1))

__device__ __forceinline__ void gbar(int i, int n) {
    __syncthreads();
    if (threadIdx.x == 0) {
        __threadfence();
        atomicAdd(&d_bar[i], 1);
        while (atomicAdd(&d_bar[i], 0) < n) { __nanosleep(64); }
    }
    __syncthreads();
}

// ---------------- K0: zero scratch + detect index width ----------------
__global__ void k_zero(const void* eidx, const void* bat,
                       long long e2w, long long nw) {
    int idx = blockIdx.x * blockDim.x + threadIdx.x;
    int stride = gridDim.x * blockDim.x;
    for (int i = idx; i < MAXB * 128; i += stride) d_A[i] = 0.f;
    for (int i = idx; i < MAXB * 64;  i += stride) d_gx[i] = 0.f;
    for (int i = idx; i < MAXB;       i += stride) d_hist[i] = 0;
    for (int i = idx; i < 128;        i += stride) {
        d_Q[i] = 0.f; d_S1[i] = 0.f; d_Q1[i] = 0.f; d_S2[i] = 0.f; d_Q2[i] = 0.f;
    }
    if (idx < 8) d_bar[idx] = 0;
    if (blockIdx.x == 0 && threadIdx.x < 32) {
        const unsigned* we = (const unsigned*)eidx;
        const unsigned* wb = (const unsigned*)bat;
        int lane = threadIdx.x;
        int nz_e = 0, nz_b = 0;
        long long se = e2w / 64; if (se < 2) se = 2;
        long long sb = nw  / 64; if (sb < 2) sb = 2;
        for (int s = 0; s < 2; ++s) {
            long long k = lane * 2 + s;
            long long pe = (k * se) | 1; if (pe >= e2w) pe = 1;
            long long pb = (k * sb) | 1; if (pb >= nw)  pb = 1;
            if (we[pe] != 0u) nz_e++;
            if (wb[pb] != 0u) nz_b++;
        }
        for (int o = 16; o > 0; o >>= 1) {
            nz_e += __shfl_xor_sync(0xffffffffu, nz_e, o);
            nz_b += __shfl_xor_sync(0xffffffffu, nz_b, o);
        }
        if (lane == 0) {
            d_f_e64 = (nz_e < 8) ? 1 : 0;
            d_f_b64 = (nz_b < 8) ? 1 : 0;
        }
    }
}

// ---------------- K1: fused wprep + histogram + gx ----------------
__global__ void k_pre(const float* __restrict__ W1a,
                      const void* __restrict__ ei, const void* __restrict__ bat,
                      const float* __restrict__ x, long long E, long long N) {
    int tid = threadIdx.x, bid = blockIdx.x;
    long long gtid = (long long)bid * 256 + tid;
    int e64 = d_f_e64, b64 = d_f_b64;

    if (gtid < 16384) {
        int k = (int)(gtid >> 7), n = (int)(gtid & 127);
        __half h = __float2half(W1a[k * 128 + n]);
        d_Wt[n * 136 + k] = *(unsigned short*)&h;
    }

    if (bid < 256) {
        __shared__ int lh[MAXB];
        for (int i = tid; i < MAXB; i += 256) lh[i] = 0;
        __syncthreads();
        long long stride = 256LL * 256;
        for (long long e = (long long)bid * 256 + tid; e < E; e += stride) {
            long long c = ldix(ei, E + e, e64);
            atomicAdd(&lh[(int)ldix(bat, c, b64)], 1);
        }
        __syncthreads();
        for (int i = tid; i < MAXB; i += 256)
            if (lh[i]) atomicAdd(&d_hist[i], lh[i]);
    }

    long long tot = N * 16;
    long long gstride = (long long)gridDim.x * 256;
    for (long long idx = gtid; idx < tot; idx += gstride) {
        long long node = idx >> 4;
        int q = (int)(idx & 15);
        int g = (int)ldix(bat, node, b64);
        float4 v = ((const float4*)x)[node * 16 + q];
        red4(d_gx + (long long)g * 64 + q * 4, v);
    }
}

// ---------------- sort pass 2: exclusive scan (+offsets table) ----------------
__global__ void k_scan() {
    __shared__ int s[MAXB];
    int t = threadIdx.x;
    int v = d_hist[t];
    s[t] = v;
    __syncthreads();
    for (int o = 1; o < MAXB; o <<= 1) {
        int u = (t >= o) ? s[t - o] : 0;
        __syncthreads();
        s[t] += u;
        __syncthreads();
    }
    d_cur[t] = s[t] - v;
    d_off[t] = s[t] - v;
    d_cnt[t] = v;
    if (t == MAXB - 1) d_off[MAXB] = s[t];
}

// ---------------- sort pass 3: scatter (block-privatized cursors) ----------------
#define CH 4096
__global__ void k_scatter(const void* __restrict__ ei, const void* __restrict__ bat,
                          long long E) {
    __shared__ int sg_[CH], sr_[CH];
    __shared__ int lh[MAXB], lbase[MAXB];
    int tid = threadIdx.x;
    long long e0 = (long long)blockIdx.x * CH;
    for (int i = tid; i < MAXB; i += 256) lh[i] = 0;
    __syncthreads();
    int e64 = d_f_e64, b64 = d_f_b64;
    for (int i = tid; i < CH; i += 256) {
        long long e = e0 + i;
        if (e < E) {
            int r = (int)ldix(ei, e, e64);
            long long c = ldix(ei, E + e, e64);
            int g = (int)ldix(bat, c, b64);
            sr_[i] = r; sg_[i] = g;
            atomicAdd(&lh[g], 1);
        } else sg_[i] = -1;
    }
    __syncthreads();
    for (int g = tid; g < MAXB; g += 256)
        if (lh[g]) lbase[g] = atomicAdd(&d_cur[g], lh[g]);
    __syncthreads();
    for (int g = tid; g < MAXB; g += 256) lh[g] = 0;
    __syncthreads();
    for (int i = tid; i < CH; i += 256) {
        int g = sg_[i];
        if (g >= 0) {
            int o = atomicAdd(&lh[g], 1);
            d_se2[lbase[g] + o] = make_int2(sr_[i], (int)(e0 + i));
        }
    }
}

// ---------------- K2: persistent pipelined mma.sync edge kernel (512 thr) ----------
// 16 warps: warp grid 8m x 2n, warp tile 16 edges x 64 cols.
__global__ __launch_bounds__(512, 1)
void k_edge(const float* __restrict__ x, const float* __restrict__ ea,
            const float* __restrict__ b1a, long long E, int ntiles) {
    extern __shared__ char smem[];
    const uint32_t sb = smem_u32(smem);
    const int tid = threadIdx.x, wid = tid >> 5, lane = tid & 31;
    const int wm = wid & 7, wn = wid >> 3;
    const int rowb = wm * 16, colb = wn * 64;

    // one-time: W tile + offsets table
    {
        const uint4* wsrc = (const uint4*)d_Wt;
        uint4* wdst = (uint4*)(smem + S_W);
        for (int i = tid; i < 2176; i += 512) wdst[i] = wsrc[i];
        int* soff = (int*)(smem + S_OFF);
        for (int i = tid; i <= MAXB; i += 512) soff[i] = d_off[i];
    }
    const int* soff = (const int*)(smem + S_OFF);

    float bb0[8], bb1[8];
    #pragma unroll
    for (int ni = 0; ni < 8; ++ni) {
        int colp = colb + ni * 8 + 2 * (lane & 3);
        bb0[ni] = b1a[colp];
        bb1[ni] = b1a[colp + 1];
    }
    const int mycol = tid & 127, myquarter = tid >> 7;   // 0..3
    float qacc = 0.f;

    // staging maps
    const int eSub = lane >> 4;                  // cp.async: 2 edges/warp-iter
    const int c4   = lane & 15;
    const int cvE  = tid >> 2;                   // convert: edge 0..127
    const int cvQ  = tid & 3;                    // quarter of 32 float4
    // ldmatrix lane-address components
    const int arow = lane & 15;
    const int akof = (lane >> 4) * 16;
    const int brow = (lane & 7) + ((lane & 16) >> 1);
    const int bkof = ((lane >> 3) & 1) * 16;
    const int gstride = gridDim.x;

    __syncthreads();   // soff ready

    // ---- prologue ----
    {
        long long e0 = (long long)blockIdx.x * 128;
        if (tid < 128) {
            long long e = e0 + tid;
            int4 v;
            if (e < E) {
                int2 se = d_se2[e];
                int ei32 = (int)e, g = 0;
                #pragma unroll
                for (int b = 512; b; b >>= 1) {
                    int ng = g + b;
                    if (ng <= MAXB - 1 && soff[ng] <= ei32) g = ng;
                }
                v = make_int4(se.x, g, se.y, 0);
            } else v = make_int4(0, -1, 0, 0);
            *(int4*)(smem + S_IDX0 + tid * 16) = v;
        }
        __syncthreads();
        #pragma unroll
        for (int i = 0; i < 4; ++i) {
            int e = wid * 8 + i * 2 + eSub;
            int4 iv = *(const int4*)(smem + S_IDX0 + e * 16);
            cpa16(sb + S_RAW + (uint32_t)e * 528 + c4 * 16,       x + (size_t)iv.x * 64 + c4 * 4);
            cpa16(sb + S_RAW + (uint32_t)e * 528 + 256 + c4 * 16, ea + (size_t)iv.z * 64 + c4 * 4);
        }
        asm volatile("cp.async.commit_group;" ::: "memory");
    }

    for (int t = blockIdx.x; t < ntiles; t += gstride) {
        const int p = ((t / gstride) & 1);
        const uint32_t sip = (p ? S_IDX1 : S_IDX0);
        const uint32_t sin = (p ? S_IDX0 : S_IDX1);

        asm volatile("cp.async.wait_group 0;" ::: "memory");
        __syncthreads();

        // ---- convert raw fp32 -> fp16 hi/lo (8 float4 per thread) ----
        {
            const char* rp = smem + S_RAW + (size_t)cvE * 528;
            char* ah = smem + S_A + (size_t)cvE * 272;
            char* al = ah + 34816;
            #pragma unroll
            for (int j = 0; j < 8; ++j) {
                int fq = cvQ * 8 + j;                 // 0..31
                int rof = (fq < 16) ? fq * 16 : 256 + (fq - 16) * 16;
                float4 v = *(const float4*)(rp + rof);
                __half2 h01 = __floats2half2_rn(v.x, v.y);
                __half2 h23 = __floats2half2_rn(v.z, v.w);
                float2 f01 = __half22float2(h01);
                float2 f23 = __half22float2(h23);
                __half2 l01 = __floats2half2_rn(v.x - f01.x, v.y - f01.y);
                __half2 l23 = __floats2half2_rn(v.z - f23.x, v.w - f23.y);
                *(uint2*)(ah + fq * 8) = make_uint2(*(uint32_t*)&h01, *(uint32_t*)&h23);
                *(uint2*)(al + fq * 8) = make_uint2(*(uint32_t*)&l01, *(uint32_t*)&l23);
            }
        }

        // ---- indices for next tile ----
        const long long tn = (long long)t + gstride;
        const bool have_next = tn < ntiles;
        if (have_next && tid < 128) {
            long long e = tn * 128 + tid;
            int4 v;
            if (e < E) {
                int2 se = d_se2[e];
                int ei32 = (int)e, g = 0;
                #pragma unroll
                for (int b = 512; b; b >>= 1) {
                    int ng = g + b;
                    if (ng <= MAXB - 1 && soff[ng] <= ei32) g = ng;
                }
                v = make_int4(se.x, g, se.y, 0);
            } else v = make_int4(0, -1, 0, 0);
            *(int4*)(smem + sin + tid * 16) = v;
        }
        __syncthreads();

        // ---- issue cp.async for next tile ----
        if (have_next) {
            #pragma unroll
            for (int i = 0; i < 4; ++i) {
                int e = wid * 8 + i * 2 + eSub;
                int4 iv = *(const int4*)(smem + sin + e * 16);
                cpa16(sb + S_RAW + (uint32_t)e * 528 + c4 * 16,       x + (size_t)iv.x * 64 + c4 * 4);
                cpa16(sb + S_RAW + (uint32_t)e * 528 + 256 + c4 * 16, ea + (size_t)iv.z * 64 + c4 * 4);
            }
            asm volatile("cp.async.commit_group;" ::: "memory");
        }

        // ---- MMA mainloop: warp tile 16e x 64j, 2 products ----
        float c[8][4];
        #pragma unroll
        for (int ni = 0; ni < 8; ++ni)
            #pragma unroll
            for (int j = 0; j < 4; ++j) c[ni][j] = 0.f;

        #pragma unroll
        for (int kk = 0; kk < 8; ++kk) {
            uint32_t ah[4], al_[4];
            uint32_t aaddr = sb + S_A + (uint32_t)(rowb + arow) * 272 + kk * 32 + akof;
            LDSM4(ah, aaddr);
            LDSM4(al_, aaddr + 34816u);
            #pragma unroll
            for (int np = 0; np < 4; ++np) {
                uint32_t baddr = sb + S_W + (uint32_t)(colb + np * 16 + brow) * 272
                                 + kk * 32 + bkof;
                uint32_t bh[4];
                LDSM4(bh, baddr);
                MMA16816(c[np * 2 + 0], ah,  bh[0], bh[1]);
                MMA16816(c[np * 2 + 1], ah,  bh[2], bh[3]);
                MMA16816(c[np * 2 + 0], al_, bh[0], bh[1]);
                MMA16816(c[np * 2 + 1], al_, bh[2], bh[3]);
            }
        }
        __syncthreads();                 // A fp16 consumed; S_A reusable

        int g0   = *(const int*)(smem + sip + 4);
        int g127 = *(const int*)(smem + sip + 127 * 16 + 4);
        bool mono = (g0 == g127) && (g0 >= 0);

        if (mono) {
            // ---- register-space column reduction ----
            float* sumb = (float*)(smem + S_A);        // [8][128]
            float* qb   = sumb + 1024;                 // [8][128]
            #pragma unroll
            for (int ni = 0; ni < 8; ++ni) {
                float a0 = leaky(c[ni][0] + bb0[ni]);
                float a1 = leaky(c[ni][1] + bb1[ni]);
                float a2 = leaky(c[ni][2] + bb0[ni]);
                float a3 = leaky(c[ni][3] + bb1[ni]);
                float s0 = a0 + a2, s1 = a1 + a3;
                float qq0 = a0 * a0 + a2 * a2;
                float qq1 = a1 * a1 + a3 * a3;
                #pragma unroll
                for (int o = 4; o < 32; o <<= 1) {
                    s0  += __shfl_xor_sync(0xffffffffu, s0,  o);
                    s1  += __shfl_xor_sync(0xffffffffu, s1,  o);
                    qq0 += __shfl_xor_sync(0xffffffffu, qq0, o);
                    qq1 += __shfl_xor_sync(0xffffffffu, qq1, o);
                }
                if (lane < 4) {
                    int col = colb + ni * 8 + lane * 2;
                    *(float2*)(sumb + wm * 128 + col) = make_float2(s0, s1);
                    *(float2*)(qb   + wm * 128 + col) = make_float2(qq0, qq1);
                }
            }
            __syncthreads();
            if (tid < 128) {
                float s = 0.f, q = 0.f;
                #pragma unroll
                for (int w = 0; w < 8; ++w) {
                    s += sumb[w * 128 + tid];
                    q += qb[w * 128 + tid];
                }
                qacc += q;
                *(float*)(smem + S_CB + tid * 4) = s;
            }
            __syncthreads();
            if (tid < 32) {
                float4 vv = *(const float4*)((float*)(smem + S_CB) + tid * 4);
                red4(d_A + (size_t)g0 * 128 + tid * 4, vv);
            }
        } else {
            // ---- boundary tile: dump + segmented scan (32 edges/thread) ----
            float* dump = (float*)(smem + S_A);
            {
                int rA = rowb + (lane >> 2);
                int rB = rA + 8;
                #pragma unroll
                for (int ni = 0; ni < 8; ++ni) {
                    int colp = colb + ni * 8 + 2 * (lane & 3);
                    float2 vA = make_float2(leaky(c[ni][0] + bb0[ni]),
                                            leaky(c[ni][1] + bb1[ni]));
                    float2 vB = make_float2(leaky(c[ni][2] + bb0[ni]),
                                            leaky(c[ni][3] + bb1[ni]));
                    *(float2*)(dump + rA * 132 + colp) = vA;
                    *(float2*)(dump + rB * 132 + colp) = vB;
                }
            }
            __syncthreads();
            float acc = 0.f;
            int curg = -1;
            const float* dp = dump + (myquarter * 32) * 132 + mycol;
            const char* sgp = smem + sip + (myquarter * 32) * 16 + 4;
            for (int e = 0; e < 32; ++e) {
                int gg = *(const int*)(sgp + e * 16);
                float v = dp[e * 132];
                if (gg != curg) {
                    if (curg >= 0) redf(d_A + (size_t)curg * 128 + mycol, acc);
                    acc = 0.f;
                    curg = gg;
                }
                if (gg >= 0) { acc += v; qacc += v * v; }
            }
            if (curg >= 0) redf(d_A + (size_t)curg * 128 + mycol, acc);
            __syncthreads();
        }
    }

    atomicAdd(&d_Q[mycol], qacc);
}

// ---------------- fused tail: stats -> t2 -> g1 -> g2 -> g3 ----------------
__global__ void k_tail(const float* __restrict__ g1a, const float* __restrict__ be1a,
                       const float* __restrict__ b2a, const float* __restrict__ W2a,
                       const float* __restrict__ W1b, const float* __restrict__ b1b,
                       const float* __restrict__ W2b, const float* __restrict__ b2b,
                       const float* __restrict__ g1b, const float* __restrict__ be1b,
                       const float* __restrict__ W3b, const float* __restrict__ b3b,
                       const float* __restrict__ g2b, const float* __restrict__ be2b,
                       float Ef, float Bf, int B, int ngrid,
                       float* __restrict__ out) {
    __shared__ float sh1[128], sh2[128], sgx[64];
    int blk = blockIdx.x, tid = threadIdx.x;

    if (blk < 128) {
        float s = 0.f;
        for (int b = tid; b < B; b += 128) s += d_A[b * 128 + blk];
        sh1[tid] = s;
        __syncthreads();
        for (int o = 64; o; o >>= 1) {
            if (tid < o) sh1[tid] += sh1[tid + o];
            __syncthreads();
        }
        if (tid == 0) {
            float m = sh1[0] / Ef;
            float v = d_Q[blk] / Ef - m * m;
            float sc = g1a[blk] * rsqrtf(v + EPS);
            d_s1[blk] = sc;
            d_t1[blk] = be1a[blk] - m * sc;
        }
    }
    gbar(0, ngrid);

    if (blk < 128) {
        sh1[tid] = d_t1[tid] * W2a[tid * 128 + blk];
        __syncthreads();
        for (int o = 64; o; o >>= 1) {
            if (tid < o) sh1[tid] += sh1[tid + o];
            __syncthreads();
        }
        if (tid == 0) d_t2[blk] = sh1[0] + b2a[blk];
    }
    gbar(1, ngrid);

    if (blk < B) {
        int b = blk, j = tid;
        sh1[j] = d_A[b * 128 + j] * d_s1[j];
        if (j < 64) sgx[j] = d_gx[b * 64 + j];
        __syncthreads();
        float cf = (float)d_cnt[b];
        float ga = d_t2[j] * cf;
        #pragma unroll 8
        for (int k = 0; k < 128; ++k) ga += sh1[k] * W2a[k * 128 + j];
        sh2[j] = ga;
        __syncthreads();
        float z = b1b[j];
        #pragma unroll 8
        for (int i = 0; i < 64; ++i)  z += sgx[i] * W1b[i * 128 + j];
        #pragma unroll 8
        for (int i = 0; i < 128; ++i) z += sh2[i] * W1b[(64 + i) * 128 + j];
        float a = leaky(z);
        d_a1[b * 128 + j] = a;
        atomicAdd(&d_S1[j], a);
        atomicAdd(&d_Q1[j], a * a);
    }
    gbar(2, ngrid);

    if (blk < B) {
        int b = blk, j = tid;
        float m = d_S1[j] / Bf;
        float v = d_Q1[j] / Bf - m * m;
        float s = g1b[j] * rsqrtf(v + EPS);
        float tt = be1b[j] - m * s;
        sh1[j] = d_a1[b * 128 + j] * s + tt;
        __syncthreads();
        float z = b2b[j];
        #pragma unroll 8
        for (int k = 0; k < 128; ++k) z += sh1[k] * W2b[k * 128 + j];
        float a = leaky(z);
        d_a2[b * 128 + j] = a;
        atomicAdd(&d_S2[j], a);
        atomicAdd(&d_Q2[j], a * a);
        __syncthreads();
    }
    gbar(3, ngrid);

    if (blk < B) {
        int b = blk, j = tid;
        float m = d_S2[j] / Bf;
        float v = d_Q2[j] / Bf - m * m;
        float s = g2b[j] * rsqrtf(v + EPS);
        float tt = be2b[j] - m * s;
        sh1[j] = d_a2[b * 128 + j] * s + tt;
        __syncthreads();
        float z = b3b[j];
        #pragma unroll 8
        for (int k = 0; k < 128; ++k) z += sh1[k] * W3b[k * 128 + j];
        out[b * 128 + j] = z;
    }
}

// ---------------- launch ----------------
extern "C" void kernel_launch(void* const* d_in, const int* in_sizes, int n_in,
                              void* d_out, int out_size) {
    const float* x    = (const float*)d_in[0];
    const void*  ei   = d_in[1];
    const float* ea   = (const float*)d_in[2];
    const void*  bat  = d_in[4];
    const float* W1a  = (const float*)d_in[5];
    const float* b1a  = (const float*)d_in[6];
    const float* g1a  = (const float*)d_in[7];
    const float* be1a = (const float*)d_in[8];
    const float* W2a  = (const float*)d_in[9];
    const float* b2a  = (const float*)d_in[10];
    const float* W1b  = (const float*)d_in[11];
    const float* b1b  = (const float*)d_in[12];
    const float* g1b  = (const float*)d_in[13];
    const float* be1b = (const float*)d_in[14];
    const float* W2b  = (const float*)d_in[15];
    const float* b2b  = (const float*)d_in[16];
    const float* g2b  = (const float*)d_in[17];
    const float* be2b = (const float*)d_in[18];
    const float* W3b  = (const float*)d_in[19];
    const float* b3b  = (const float*)d_in[20];

    long long N = (long long)in_sizes[0] / 64;
    long long E = (long long)in_sizes[2] / 64;
    int B = in_sizes[3];
    if (B > MAXB) B = MAXB;

    static int smem_set = 0;
    if (!smem_set) {
        cudaFuncSetAttribute(k_edge, cudaFuncAttributeMaxDynamicSharedMemorySize, SMEM_TOT);
        smem_set = 1;
    }

    k_zero<<<256, 256>>>(ei, bat, 2 * E, N);

    int gridP = (int)((N * 16 + 255) / 256);
    if (gridP < 256) gridP = 256;
    k_pre<<<gridP, 256>>>(W1a, ei, bat, x, E, N);

    k_scan<<<1, MAXB>>>();
    int gridS = (int)((E + CH - 1) / CH);
    k_scatter<<<gridS, 256>>>(ei, bat, E);

    int ntiles = (int)((E + 127) / 128);
    int grid = ntiles < 148 ? ntiles : 148;
    k_edge<<<grid, 512, SMEM_TOT>>>(x, ea, b1a, E, ntiles);

    int ng = B > 128 ? B : 128;
    k_tail<<<ng, 128>>>(g1a, be1a, b2a, W2a, W1b, b1b, W2b, b2b, g1b, be1b,
                        W3b, b3b, g2b, be2b, (float)E, (float)B, B, ng,
                        (float*)d_out);
}

// round 15
// speedup vs baseline: 1.2080x; 1.2080x over previous
#include <cuda_runtime.h>
#include <cuda_fp16.h>
#include <cstdint>

#define MAXB  1024
#define EMAX  (1 << 20)
#define NMAX  65536
#define EPS   1e-5f
#define SLOPE 0.01f

// ---------------- static device scratch (no allocations allowed) ----------------
__device__ __align__(16) float d_A [MAXB * 128];
__device__ __align__(16) float d_gx[MAXB * 64];
__device__            int   d_cnt[MAXB];
__device__ __align__(16) float d_Q [128];
__device__ __align__(16) float d_s1[128], d_t1[128], d_t2[128];
__device__ __align__(16) float d_S1[128], d_Q1[128], d_S2[128], d_Q2[128];
__device__ __align__(16) float d_a1[MAXB * 128], d_a2[MAXB * 128];
__device__ __align__(16) unsigned short d_Wt[17408];  // W^T fp16 hi [128][136]
__device__ __align__(16) __half d_xh[NMAX * 64];      // x fp16 hi
__device__ __align__(16) __half d_xl[NMAX * 64];      // x fp16 lo
__device__ __align__(16) int4  d_se[EMAX];            // sorted edges {row, g, e_orig, 0}
__device__            int   d_hist[MAXB], d_cur[MAXB];
__device__            int   d_bar[8];
__device__            int   d_f_e64, d_f_b64;

// ---------------- smem layout of k_edge ----------------
#define S_IDX0  0            // int4 {row,g,eorig,0} x 128
#define S_IDX1  2048
#define S_CB    4096         // 512B column buffer
#define S_W     6144         // Whi [128][272B] = 34816
#define S_A0    40960        // tile buffer 0: Ahi|Alo (69632); reused as f32 dump
#define S_A1    110592       // tile buffer 1
#define S_RAW   180224       // raw fp32 ea [128][272B] = 34816
#define SMEM_TOT 215040

// ---------------- helpers ----------------
__device__ __forceinline__ void red4(float* p, float4 v) {
    asm volatile("red.global.add.v4.f32 [%0], {%1,%2,%3,%4};"
                 :: "l"(p), "f"(v.x), "f"(v.y), "f"(v.z), "f"(v.w) : "memory");
}
__device__ __forceinline__ void redf(float* p, float v) {
    asm volatile("red.global.add.f32 [%0], %1;" :: "l"(p), "f"(v) : "memory");
}
__device__ __forceinline__ long long ldix(const void* p, long long i, int is64) {
    return is64 ? ((const long long*)p)[i] : (long long)((const int*)p)[i];
}
__device__ __forceinline__ float leaky(float z) { return z >= 0.f ? z : SLOPE * z; }
__device__ __forceinline__ uint32_t smem_u32(const void* p) {
    uint32_t a;
    asm("{ .reg .u64 t; cvta.to.shared.u64 t, %1; cvt.u32.u64 %0, t; }" : "=r"(a) : "l"(p));
    return a;
}
__device__ __forceinline__ void cpa16(uint32_t s, const void* g) {
    asm volatile("cp.async.cg.shared.global [%0], [%1], 16;" :: "r"(s), "l"(g) : "memory");
}
#define LDSM4(r, a) \
    asm volatile("ldmatrix.sync.aligned.m8n8.x4.shared.b16 {%0,%1,%2,%3}, [%4];" \
        : "=r"((r)[0]), "=r"((r)[1]), "=r"((r)[2]), "=r"((r)[3]) : "r"(a))
#define MMA16816(c, a, b0, b1) \
    asm volatile("mma.sync.aligned.m16n8k16.row.col.f32.f16.f16.f32 " \
        "{%0,%1,%2,%3}, {%4,%5,%6,%7}, {%8,%9}, {%0,%1,%2,%3};" \
        : "+f"((c)[0]), "+f"((c)[1]), "+f"((c)[2]), "+f"((c)[3]) \
        : "r"((a)[0]), "r"((a)[1]), "r"((a)[2]), "r"((a)[3]), "r"(b0), "r"(b1))

__device__ __forceinline__ void gbar(int i, int n) {
    __syncthreads();
    if (threadIdx.x == 0) {
        __threadfence();
        atomicAdd(&d_bar[i], 1);
        while (atomicAdd(&d_bar[i], 0) < n) { __nanosleep(64); }
    }
    __syncthreads();
}

// ---------------- K0: zero scratch + detect index width ----------------
__global__ void k_zero(const void* eidx, const void* bat,
                       long long e2w, long long nw) {
    int idx = blockIdx.x * blockDim.x + threadIdx.x;
    int stride = gridDim.x * blockDim.x;
    for (int i = idx; i < MAXB * 128; i += stride) d_A[i] = 0.f;
    for (int i = idx; i < MAXB * 64;  i += stride) d_gx[i] = 0.f;
    for (int i = idx; i < MAXB;       i += stride) d_hist[i] = 0;
    for (int i = idx; i < 128;        i += stride) {
        d_Q[i] = 0.f; d_S1[i] = 0.f; d_Q1[i] = 0.f; d_S2[i] = 0.f; d_Q2[i] = 0.f;
    }
    if (idx < 8) d_bar[idx] = 0;
    if (blockIdx.x == 0 && threadIdx.x < 32) {
        const unsigned* we = (const unsigned*)eidx;
        const unsigned* wb = (const unsigned*)bat;
        int lane = threadIdx.x;
        int nz_e = 0, nz_b = 0;
        long long se = e2w / 64; if (se < 2) se = 2;
        long long sb = nw  / 64; if (sb < 2) sb = 2;
        for (int s = 0; s < 2; ++s) {
            long long k = lane * 2 + s;
            long long pe = (k * se) | 1; if (pe >= e2w) pe = 1;
            long long pb = (k * sb) | 1; if (pb >= nw)  pb = 1;
            if (we[pe] != 0u) nz_e++;
            if (wb[pb] != 0u) nz_b++;
        }
        for (int o = 16; o > 0; o >>= 1) {
            nz_e += __shfl_xor_sync(0xffffffffu, nz_e, o);
            nz_b += __shfl_xor_sync(0xffffffffu, nz_b, o);
        }
        if (lane == 0) {
            d_f_e64 = (nz_e < 8) ? 1 : 0;
            d_f_b64 = (nz_b < 8) ? 1 : 0;
        }
    }
}

// ---------------- K1: fused wprep + histogram + gx + x->fp16 ----------------
__global__ void k_pre(const float* __restrict__ W1a,
                      const void* __restrict__ ei, const void* __restrict__ bat,
                      const float* __restrict__ x, long long E, long long N) {
    int tid = threadIdx.x, bid = blockIdx.x;
    long long gtid = (long long)bid * 256 + tid;
    int e64 = d_f_e64, b64 = d_f_b64;

    if (gtid < 16384) {
        int k = (int)(gtid >> 7), n = (int)(gtid & 127);
        __half h = __float2half(W1a[k * 128 + n]);
        d_Wt[n * 136 + k] = *(unsigned short*)&h;
    }

    if (bid < 256) {
        __shared__ int lh[MAXB];
        for (int i = tid; i < MAXB; i += 256) lh[i] = 0;
        __syncthreads();
        long long stride = 256LL * 256;
        for (long long e = (long long)bid * 256 + tid; e < E; e += stride) {
            long long c = ldix(ei, E + e, e64);
            atomicAdd(&lh[(int)ldix(bat, c, b64)], 1);
        }
        __syncthreads();
        for (int i = tid; i < MAXB; i += 256)
            if (lh[i]) atomicAdd(&d_hist[i], lh[i]);
    }

    // gx + x fp16 hi/lo conversion (single pass over x)
    long long tot = N * 16;
    long long gstride = (long long)gridDim.x * 256;
    for (long long idx = gtid; idx < tot; idx += gstride) {
        long long node = idx >> 4;
        int q = (int)(idx & 15);
        int g = (int)ldix(bat, node, b64);
        float4 v = ((const float4*)x)[node * 16 + q];
        red4(d_gx + (long long)g * 64 + q * 4, v);
        __half2 h01 = __floats2half2_rn(v.x, v.y);
        __half2 h23 = __floats2half2_rn(v.z, v.w);
        float2 f01 = __half22float2(h01);
        float2 f23 = __half22float2(h23);
        __half2 l01 = __floats2half2_rn(v.x - f01.x, v.y - f01.y);
        __half2 l23 = __floats2half2_rn(v.z - f23.x, v.w - f23.y);
        *(uint2*)(d_xh + node * 64 + q * 4) = make_uint2(*(uint32_t*)&h01, *(uint32_t*)&h23);
        *(uint2*)(d_xl + node * 64 + q * 4) = make_uint2(*(uint32_t*)&l01, *(uint32_t*)&l23);
    }
}

// ---------------- sort pass 2: exclusive scan ----------------
__global__ void k_scan() {
    __shared__ int s[MAXB];
    int t = threadIdx.x;
    int v = d_hist[t];
    s[t] = v;
    __syncthreads();
    for (int o = 1; o < MAXB; o <<= 1) {
        int u = (t >= o) ? s[t - o] : 0;
        __syncthreads();
        s[t] += u;
        __syncthreads();
    }
    d_cur[t] = s[t] - v;
    d_cnt[t] = v;
}

// ---------------- sort pass 3: scatter (block-privatized cursors) ----------------
#define CH 4096
__global__ void k_scatter(const void* __restrict__ ei, const void* __restrict__ bat,
                          long long E) {
    __shared__ int sg_[CH], sr_[CH];
    __shared__ int lh[MAXB], lbase[MAXB];
    int tid = threadIdx.x;
    long long e0 = (long long)blockIdx.x * CH;
    for (int i = tid; i < MAXB; i += 256) lh[i] = 0;
    __syncthreads();
    int e64 = d_f_e64, b64 = d_f_b64;
    for (int i = tid; i < CH; i += 256) {
        long long e = e0 + i;
        if (e < E) {
            int r = (int)ldix(ei, e, e64);
            long long c = ldix(ei, E + e, e64);
            int g = (int)ldix(bat, c, b64);
            sr_[i] = r; sg_[i] = g;
            atomicAdd(&lh[g], 1);
        } else sg_[i] = -1;
    }
    __syncthreads();
    for (int g = tid; g < MAXB; g += 256)
        if (lh[g]) lbase[g] = atomicAdd(&d_cur[g], lh[g]);
    __syncthreads();
    for (int g = tid; g < MAXB; g += 256) lh[g] = 0;
    __syncthreads();
    for (int i = tid; i < CH; i += 256) {
        int g = sg_[i];
        if (g >= 0) {
            int o = atomicAdd(&lh[g], 1);
            d_se[lbase[g] + o] = make_int4(sr_[i], g, (int)(e0 + i), 0);
        }
    }
}

// ---------------- K2: persistent pipelined mma.sync edge kernel ----------------
// 256 thr, 8 warps: warp grid 4m x 2n, warp tile 32e x 64c. A double-buffered:
// x fp16 cp.async'd directly into A; only ea converted in-kernel.
__global__ __launch_bounds__(256, 1)
void k_edge(const float* __restrict__ ea, const float* __restrict__ b1a,
            long long E, int ntiles) {
    extern __shared__ char smem[];
    const uint32_t sb = smem_u32(smem);
    const int tid = threadIdx.x, wid = tid >> 5, lane = tid & 31;
    const int wm = wid & 3, wn = wid >> 2;
    const int rowb = wm * 32, colb = wn * 64;

    // one-time: W tile
    {
        const uint4* wsrc = (const uint4*)d_Wt;
        uint4* wdst = (uint4*)(smem + S_W);
        for (int i = tid; i < 2176; i += 256) wdst[i] = wsrc[i];
    }

    float bb0[8], bb1[8];
    #pragma unroll
    for (int ni = 0; ni < 8; ++ni) {
        int colp = colb + ni * 8 + 2 * (lane & 3);
        bb0[ni] = b1a[colp];
        bb1[ni] = b1a[colp + 1];
    }
    const int mycol = tid & 127, myhalf = tid >> 7;
    float qacc = 0.f;

    const int eSub = lane >> 4;                 // 2 edge-slots per warp-iter
    const int c4   = lane & 15;                 // 16 lanes per edge
    const int c4m  = c4 & 7, sel = c4 >> 3;     // x: hi (sel=0) / lo (sel=1) chunk
    const uint32_t xAoff = sel ? 34816u : 0u;
    const __half* xsrc = sel ? d_xl : d_xh;
    // ldmatrix lane-address components
    const int arow = lane & 15;
    const int akof = (lane >> 4) * 16;
    const int brow = (lane & 7) + ((lane & 16) >> 1);
    const int bkof = ((lane >> 3) & 1) * 16;
    const int gstride = gridDim.x;

    // ---- prologue: tile 0 -> buffer A0 ----
    {
        long long e0 = (long long)blockIdx.x * 128;
        if (tid < 128) {
            long long e = e0 + tid;
            int4 v = (e < E) ? d_se[e] : make_int4(0, -1, 0, 0);
            *(int4*)(smem + S_IDX0 + tid * 16) = v;
        }
        __syncthreads();
        #pragma unroll
        for (int i = 0; i < 8; ++i) {
            int e = wid * 16 + i * 2 + eSub;
            int4 iv = *(const int4*)(smem + S_IDX0 + e * 16);
            cpa16(sb + S_A0 + xAoff + (uint32_t)e * 272 + c4m * 16,
                  xsrc + (size_t)iv.x * 64 + c4m * 8);
            cpa16(sb + S_RAW + (uint32_t)e * 272 + c4 * 16,
                  ea + (size_t)iv.z * 64 + c4 * 4);
        }
        asm volatile("cp.async.commit_group;" ::: "memory");
    }

    for (int t = blockIdx.x; t < ntiles; t += gstride) {
        const int p = ((t / gstride) & 1);
        const uint32_t sip = (p ? S_IDX1 : S_IDX0);
        const uint32_t sin = (p ? S_IDX0 : S_IDX1);
        const uint32_t sab = (p ? S_A1 : S_A0);   // current tile buffer
        const uint32_t san = (p ? S_A0 : S_A1);   // next tile buffer

        asm volatile("cp.async.wait_group 0;" ::: "memory");
        __syncthreads();                 // x fp16 + ea raw (t) landed; dump(t-1) consumed

        // ---- convert ea raw fp32 -> fp16 hi/lo (cols 64..127 of A) ----
        #pragma unroll
        for (int i = 0; i < 8; ++i) {
            int e = wid * 16 + i * 2 + eSub;
            float4 v = *(const float4*)(smem + S_RAW + (size_t)e * 272 + c4 * 16);
            __half2 h01 = __floats2half2_rn(v.x, v.y);
            __half2 h23 = __floats2half2_rn(v.z, v.w);
            float2 f01 = __half22float2(h01);
            float2 f23 = __half22float2(h23);
            __half2 l01 = __floats2half2_rn(v.x - f01.x, v.y - f01.y);
            __half2 l23 = __floats2half2_rn(v.z - f23.x, v.w - f23.y);
            char* ab = smem + sab + (size_t)e * 272 + 128 + c4 * 8;
            *(uint2*)(ab)          = make_uint2(*(uint32_t*)&h01, *(uint32_t*)&h23);
            *(uint2*)(ab + 34816)  = make_uint2(*(uint32_t*)&l01, *(uint32_t*)&l23);
        }

        // ---- indices for next tile ----
        const long long tn = (long long)t + gstride;
        const bool have_next = tn < ntiles;
        if (have_next && tid < 128) {
            long long e = tn * 128 + tid;
            int4 v = (e < E) ? d_se[e] : make_int4(0, -1, 0, 0);
            *(int4*)(smem + sin + tid * 16) = v;
        }
        __syncthreads();                 // A(t) complete; next idx visible; RAW consumed

        // ---- issue cp.async for next tile (x -> san, ea -> RAW) ----
        if (have_next) {
            #pragma unroll
            for (int i = 0; i < 8; ++i) {
                int e = wid * 16 + i * 2 + eSub;
                int4 iv = *(const int4*)(smem + sin + e * 16);
                cpa16(sb + san + xAoff + (uint32_t)e * 272 + c4m * 16,
                      xsrc + (size_t)iv.x * 64 + c4m * 8);
                cpa16(sb + S_RAW + (uint32_t)e * 272 + c4 * 16,
                      ea + (size_t)iv.z * 64 + c4 * 4);
            }
            asm volatile("cp.async.commit_group;" ::: "memory");
        }

        // ---- MMA mainloop: 2 products (Ahi+Alo) x Whi ----
        float c[2][8][4];
        #pragma unroll
        for (int mi = 0; mi < 2; ++mi)
            #pragma unroll
            for (int ni = 0; ni < 8; ++ni)
                #pragma unroll
                for (int j = 0; j < 4; ++j) c[mi][ni][j] = 0.f;

        #pragma unroll
        for (int kk = 0; kk < 8; ++kk) {
            uint32_t ah[2][4], al_[2][4];
            #pragma unroll
            for (int mi = 0; mi < 2; ++mi) {
                uint32_t aaddr = sb + sab + (uint32_t)(rowb + mi * 16 + arow) * 272
                                 + kk * 32 + akof;
                LDSM4(ah[mi], aaddr);
                LDSM4(al_[mi], aaddr + 34816u);
            }
            #pragma unroll
            for (int np = 0; np < 4; ++np) {
                uint32_t baddr = sb + S_W + (uint32_t)(colb + np * 16 + brow) * 272
                                 + kk * 32 + bkof;
                uint32_t bh[4];
                LDSM4(bh, baddr);
                #pragma unroll
                for (int mi = 0; mi < 2; ++mi) {
                    MMA16816(c[mi][np * 2 + 0], ah[mi],  bh[0], bh[1]);
                    MMA16816(c[mi][np * 2 + 1], ah[mi],  bh[2], bh[3]);
                    MMA16816(c[mi][np * 2 + 0], al_[mi], bh[0], bh[1]);
                    MMA16816(c[mi][np * 2 + 1], al_[mi], bh[2], bh[3]);
                }
            }
        }
        __syncthreads();                 // A(t) consumed; sab reusable as dump

        // ---- dump bias+leaky activations to smem (sab as f32 [128][132]) ----
        float* dump = (float*)(smem + sab);
        #pragma unroll
        for (int mi = 0; mi < 2; ++mi) {
            int rA = rowb + mi * 16 + (lane >> 2);
            int rB = rA + 8;
            #pragma unroll
            for (int ni = 0; ni < 8; ++ni) {
                int colp = colb + ni * 8 + 2 * (lane & 3);
                float2 vA = make_float2(leaky(c[mi][ni][0] + bb0[ni]),
                                        leaky(c[mi][ni][1] + bb1[ni]));
                float2 vB = make_float2(leaky(c[mi][ni][2] + bb0[ni]),
                                        leaky(c[mi][ni][3] + bb1[ni]));
                *(float2*)(dump + rA * 132 + colp) = vA;
                *(float2*)(dump + rB * 132 + colp) = vB;
            }
        }
        __syncthreads();

        // ---- column scan: sum 64 edges per (col, half); flush by graph ----
        int g0   = *(const int*)(smem + sip + 4);
        int g127 = *(const int*)(smem + sip + 127 * 16 + 4);
        bool mono = (g0 == g127) && (g0 >= 0);
        if (mono) {
            float acc = 0.f;
            const float* dp = dump + (myhalf * 64) * 132 + mycol;
            #pragma unroll 8
            for (int e = 0; e < 64; ++e) {
                float v = dp[e * 132];
                acc += v;
                qacc += v * v;
            }
            float* cb = (float*)(smem + S_CB);
            cb[myhalf * 128 + mycol] = acc;
            __syncthreads();
            if (tid < 128) cb[tid] = cb[tid] + cb[128 + tid];
            __syncthreads();
            if (tid < 32) {
                float4 vv = *(const float4*)((float*)(smem + S_CB) + tid * 4);
                red4(d_A + (size_t)g0 * 128 + tid * 4, vv);
            }
        } else {
            float acc = 0.f;
            int curg = -1;
            const float* dp = dump + (myhalf * 64) * 132 + mycol;
            const char* sgp = smem + sip + (myhalf * 64) * 16 + 4;
            for (int e = 0; e < 64; ++e) {
                int gg = *(const int*)(sgp + e * 16);
                float v = dp[e * 132];
                if (gg != curg) {
                    if (curg >= 0) redf(d_A + (size_t)curg * 128 + mycol, acc);
                    acc = 0.f;
                    curg = gg;
                }
                if (gg >= 0) { acc += v; qacc += v * v; }
            }
            if (curg >= 0) redf(d_A + (size_t)curg * 128 + mycol, acc);
            __syncthreads();
        }
    }

    atomicAdd(&d_Q[mycol], qacc);
}

// ---------------- fused tail: stats -> t2 -> g1 -> g2 -> g3 ----------------
__global__ void k_tail(const float* __restrict__ g1a, const float* __restrict__ be1a,
                       const float* __restrict__ b2a, const float* __restrict__ W2a,
                       const float* __restrict__ W1b, const float* __restrict__ b1b,
                       const float* __restrict__ W2b, const float* __restrict__ b2b,
                       const float* __restrict__ g1b, const float* __restrict__ be1b,
                       const float* __restrict__ W3b, const float* __restrict__ b3b,
                       const float* __restrict__ g2b, const float* __restrict__ be2b,
                       float Ef, float Bf, int B, int ngrid,
                       float* __restrict__ out) {
    __shared__ float sh1[128], sh2[128], sgx[64];
    int blk = blockIdx.x, tid = threadIdx.x;

    if (blk < 128) {
        float s = 0.f;
        for (int b = tid; b < B; b += 128) s += d_A[b * 128 + blk];
        sh1[tid] = s;
        __syncthreads();
        for (int o = 64; o; o >>= 1) {
            if (tid < o) sh1[tid] += sh1[tid + o];
            __syncthreads();
        }
        if (tid == 0) {
            float m = sh1[0] / Ef;
            float v = d_Q[blk] / Ef - m * m;
            float sc = g1a[blk] * rsqrtf(v + EPS);
            d_s1[blk] = sc;
            d_t1[blk] = be1a[blk] - m * sc;
        }
    }
    gbar(0, ngrid);

    if (blk < 128) {
        sh1[tid] = d_t1[tid] * W2a[tid * 128 + blk];
        __syncthreads();
        for (int o = 64; o; o >>= 1) {
            if (tid < o) sh1[tid] += sh1[tid + o];
            __syncthreads();
        }
        if (tid == 0) d_t2[blk] = sh1[0] + b2a[blk];
    }
    gbar(1, ngrid);

    if (blk < B) {
        int b = blk, j = tid;
        sh1[j] = d_A[b * 128 + j] * d_s1[j];
        if (j < 64) sgx[j] = d_gx[b * 64 + j];
        __syncthreads();
        float cf = (float)d_cnt[b];
        float ga = d_t2[j] * cf;
        #pragma unroll 8
        for (int k = 0; k < 128; ++k) ga += sh1[k] * W2a[k * 128 + j];
        sh2[j] = ga;
        __syncthreads();
        float z = b1b[j];
        #pragma unroll 8
        for (int i = 0; i < 64; ++i)  z += sgx[i] * W1b[i * 128 + j];
        #pragma unroll 8
        for (int i = 0; i < 128; ++i) z += sh2[i] * W1b[(64 + i) * 128 + j];
        float a = leaky(z);
        d_a1[b * 128 + j] = a;
        atomicAdd(&d_S1[j], a);
        atomicAdd(&d_Q1[j], a * a);
    }
    gbar(2, ngrid);

    if (blk < B) {
        int b = blk, j = tid;
        float m = d_S1[j] / Bf;
        float v = d_Q1[j] / Bf - m * m;
        float s = g1b[j] * rsqrtf(v + EPS);
        float tt = be1b[j] - m * s;
        sh1[j] = d_a1[b * 128 + j] * s + tt;
        __syncthreads();
        float z = b2b[j];
        #pragma unroll 8
        for (int k = 0; k < 128; ++k) z += sh1[k] * W2b[k * 128 + j];
        float a = leaky(z);
        d_a2[b * 128 + j] = a;
        atomicAdd(&d_S2[j], a);
        atomicAdd(&d_Q2[j], a * a);
        __syncthreads();
    }
    gbar(3, ngrid);

    if (blk < B) {
        int b = blk, j = tid;
        float m = d_S2[j] / Bf;
        float v = d_Q2[j] / Bf - m * m;
        float s = g2b[j] * rsqrtf(v + EPS);
        float tt = be2b[j] - m * s;
        sh1[j] = d_a2[b * 128 + j] * s + tt;
        __syncthreads();
        float z = b3b[j];
        #pragma unroll 8
        for (int k = 0; k < 128; ++k) z += sh1[k] * W3b[k * 128 + j];
        out[b * 128 + j] = z;
    }
}

// ---------------- launch ----------------
extern "C" void kernel_launch(void* const* d_in, const int* in_sizes, int n_in,
                              void* d_out, int out_size) {
    const float* x    = (const float*)d_in[0];
    const void*  ei   = d_in[1];
    const float* ea   = (const float*)d_in[2];
    const void*  bat  = d_in[4];
    const float* W1a  = (const float*)d_in[5];
    const float* b1a  = (const float*)d_in[6];
    const float* g1a  = (const float*)d_in[7];
    const float* be1a = (const float*)d_in[8];
    const float* W2a  = (const float*)d_in[9];
    const float* b2a  = (const float*)d_in[10];
    const float* W1b  = (const float*)d_in[11];
    const float* b1b  = (const float*)d_in[12];
    const float* g1b  = (const float*)d_in[13];
    const float* be1b = (const float*)d_in[14];
    const float* W2b  = (const float*)d_in[15];
    const float* b2b  = (const float*)d_in[16];
    const float* g2b  = (const float*)d_in[17];
    const float* be2b = (const float*)d_in[18];
    const float* W3b  = (const float*)d_in[19];
    const float* b3b  = (const float*)d_in[20];

    long long N = (long long)in_sizes[0] / 64;
    long long E = (long long)in_sizes[2] / 64;
    int B = in_sizes[3];
    if (B > MAXB) B = MAXB;

    static int smem_set = 0;
    if (!smem_set) {
        cudaFuncSetAttribute(k_edge, cudaFuncAttributeMaxDynamicSharedMemorySize, SMEM_TOT);
        smem_set = 1;
    }

    k_zero<<<256, 256>>>(ei, bat, 2 * E, N);

    int gridP = (int)((N * 16 + 255) / 256);
    if (gridP < 256) gridP = 256;
    k_pre<<<gridP, 256>>>(W1a, ei, bat, x, E, N);

    k_scan<<<1, MAXB>>>();
    int gridS = (int)((E + CH - 1) / CH);
    k_scatter<<<gridS, 256>>>(ei, bat, E);

    int ntiles = (int)((E + 127) / 128);
    int grid = ntiles < 148 ? ntiles : 148;
    k_edge<<<grid, 256, SMEM_TOT>>>(ea, b1a, E, ntiles);

    int ng = B > 128 ? B : 128;
    k_tail<<<ng, 128>>>(g1a, be1a, b2a, W2a, W1b, b1b, W2b, b2b, g1b, be1b,
                        W3b, b3b, g2b, be2b, (float)E, (float)B, B, ng,
                        (float*)d_out);
}

// round 16
// speedup vs baseline: 1.2391x; 1.0257x over previous
#include <cuda_runtime.h>
#include <cuda_fp16.h>
#include <cstdint>

#define MAXB  1024
#define EMAX  (1 << 20)
#define NMAX  65536
#define EPS   1e-5f
#define SLOPE 0.01f

// ---------------- static device scratch (no allocations allowed) ----------------
__device__ __align__(16) float d_A [MAXB * 128];
__device__ __align__(16) float d_gx[MAXB * 64];
__device__            int   d_cnt[MAXB];
__device__ __align__(16) float d_Q [128];
__device__ __align__(16) float d_s1[128], d_t1[128], d_t2[128];
__device__ __align__(16) float d_S1[128], d_Q1[128], d_S2[128], d_Q2[128];
__device__ __align__(16) float d_a1[MAXB * 128], d_a2[MAXB * 128];
__device__ __align__(16) unsigned short d_Wt[17408];  // W^T fp16 hi [128][136]
__device__ __align__(16) __half d_xh[NMAX * 64];      // x fp16 hi
__device__ __align__(16) __half d_xl[NMAX * 64];      // x fp16 lo
__device__ __align__(16) int4  d_se[EMAX];            // sorted edges {row, g, e_orig, 0}
__device__            int   d_hist[MAXB], d_cur[MAXB];
__device__            int   d_bar[8];
__device__            int   d_f_e64, d_f_b64;

// ---------------- smem layout of k_edge ----------------
#define S_IDX0  0            // int4 {row,g,eorig,0} x 128
#define S_IDX1  2048
#define S_CB    4096         // 1KB halves buffer + 512B fold buffer
#define S_W     6144         // Whi [128][272B] = 34816
#define S_A0    40960        // tile buffer 0: Ahi|Alo (69632); reused as f32 dump
#define S_A1    110592       // tile buffer 1
#define S_RAW   180224       // raw fp32 ea [128][272B] = 34816
#define SMEM_TOT 215040

// ---------------- helpers ----------------
__device__ __forceinline__ void red4(float* p, float4 v) {
    asm volatile("red.global.add.v4.f32 [%0], {%1,%2,%3,%4};"
                 :: "l"(p), "f"(v.x), "f"(v.y), "f"(v.z), "f"(v.w) : "memory");
}
__device__ __forceinline__ void redf(float* p, float v) {
    asm volatile("red.global.add.f32 [%0], %1;" :: "l"(p), "f"(v) : "memory");
}
__device__ __forceinline__ long long ldix(const void* p, long long i, int is64) {
    return is64 ? ((const long long*)p)[i] : (long long)((const int*)p)[i];
}
__device__ __forceinline__ float leaky(float z) { return z >= 0.f ? z : SLOPE * z; }
__device__ __forceinline__ uint32_t smem_u32(const void* p) {
    uint32_t a;
    asm("{ .reg .u64 t; cvta.to.shared.u64 t, %1; cvt.u32.u64 %0, t; }" : "=r"(a) : "l"(p));
    return a;
}
__device__ __forceinline__ void cpa16(uint32_t s, const void* g) {
    asm volatile("cp.async.cg.shared.global [%0], [%1], 16;" :: "r"(s), "l"(g) : "memory");
}
#define LDSM4(r, a) \
    asm volatile("ldmatrix.sync.aligned.m8n8.x4.shared.b16 {%0,%1,%2,%3}, [%4];" \
        : "=r"((r)[0]), "=r"((r)[1]), "=r"((r)[2]), "=r"((r)[3]) : "r"(a))
#define MMA16816(c, a, b0, b1) \
    asm volatile("mma.sync.aligned.m16n8k16.row.col.f32.f16.f16.f32 " \
        "{%0,%1,%2,%3}, {%4,%5,%6,%7}, {%8,%9}, {%0,%1,%2,%3};" \
        : "+f"((c)[0]), "+f"((c)[1]), "+f"((c)[2]), "+f"((c)[3]) \
        : "r"((a)[0]), "r"((a)[1]), "r"((a)[2]), "r"((a)[3]), "r"(b0), "r"(b1))

__device__ __forceinline__ void gbar(int i, int n) {
    __syncthreads();
    if (threadIdx.x == 0) {
        __threadfence();
        atomicAdd(&d_bar[i], 1);
        while (atomicAdd(&d_bar[i], 0) < n) { __nanosleep(64); }
    }
    __syncthreads();
}

// flush accumulated column sums for graph g (all 256 threads participate)
__device__ __forceinline__ void flush_cols(char* smem, int g, float& acc,
                                           int tid, int mycol, int myhalf) {
    float* cb  = (float*)(smem + S_CB);
    float* cb2 = (float*)(smem + S_CB + 1024);
    cb[myhalf * 128 + mycol] = acc;
    __syncthreads();
    if (tid < 128) cb2[tid] = cb[tid] + cb[128 + tid];
    __syncthreads();
    if (tid < 32) {
        float4 vv = *(const float4*)(cb2 + tid * 4);
        red4(d_A + (size_t)g * 128 + tid * 4, vv);
    }
    acc = 0.f;
}

// ---------------- K0: zero scratch + detect index width ----------------
__global__ void k_zero(const void* eidx, const void* bat,
                       long long e2w, long long nw) {
    int idx = blockIdx.x * blockDim.x + threadIdx.x;
    int stride = gridDim.x * blockDim.x;
    for (int i = idx; i < MAXB * 128; i += stride) d_A[i] = 0.f;
    for (int i = idx; i < MAXB * 64;  i += stride) d_gx[i] = 0.f;
    for (int i = idx; i < MAXB;       i += stride) d_hist[i] = 0;
    for (int i = idx; i < 128;        i += stride) {
        d_Q[i] = 0.f; d_S1[i] = 0.f; d_Q1[i] = 0.f; d_S2[i] = 0.f; d_Q2[i] = 0.f;
    }
    if (idx < 8) d_bar[idx] = 0;
    if (blockIdx.x == 0 && threadIdx.x < 32) {
        const unsigned* we = (const unsigned*)eidx;
        const unsigned* wb = (const unsigned*)bat;
        int lane = threadIdx.x;
        int nz_e = 0, nz_b = 0;
        long long se = e2w / 64; if (se < 2) se = 2;
        long long sb = nw  / 64; if (sb < 2) sb = 2;
        for (int s = 0; s < 2; ++s) {
            long long k = lane * 2 + s;
            long long pe = (k * se) | 1; if (pe >= e2w) pe = 1;
            long long pb = (k * sb) | 1; if (pb >= nw)  pb = 1;
            if (we[pe] != 0u) nz_e++;
            if (wb[pb] != 0u) nz_b++;
        }
        for (int o = 16; o > 0; o >>= 1) {
            nz_e += __shfl_xor_sync(0xffffffffu, nz_e, o);
            nz_b += __shfl_xor_sync(0xffffffffu, nz_b, o);
        }
        if (lane == 0) {
            d_f_e64 = (nz_e < 8) ? 1 : 0;
            d_f_b64 = (nz_b < 8) ? 1 : 0;
        }
    }
}

// ---------------- K1: fused wprep + histogram + gx + x->fp16 ----------------
__global__ void k_pre(const float* __restrict__ W1a,
                      const void* __restrict__ ei, const void* __restrict__ bat,
                      const float* __restrict__ x, long long E, long long N) {
    int tid = threadIdx.x, bid = blockIdx.x;
    long long gtid = (long long)bid * 256 + tid;
    int e64 = d_f_e64, b64 = d_f_b64;

    if (gtid < 16384) {
        int k = (int)(gtid >> 7), n = (int)(gtid & 127);
        __half h = __float2half(W1a[k * 128 + n]);
        d_Wt[n * 136 + k] = *(unsigned short*)&h;
    }

    if (bid < 256) {
        __shared__ int lh[MAXB];
        for (int i = tid; i < MAXB; i += 256) lh[i] = 0;
        __syncthreads();
        long long stride = 256LL * 256;
        for (long long e = (long long)bid * 256 + tid; e < E; e += stride) {
            long long c = ldix(ei, E + e, e64);
            atomicAdd(&lh[(int)ldix(bat, c, b64)], 1);
        }
        __syncthreads();
        for (int i = tid; i < MAXB; i += 256)
            if (lh[i]) atomicAdd(&d_hist[i], lh[i]);
    }

    long long tot = N * 16;
    long long gstride = (long long)gridDim.x * 256;
    for (long long idx = gtid; idx < tot; idx += gstride) {
        long long node = idx >> 4;
        int q = (int)(idx & 15);
        int g = (int)ldix(bat, node, b64);
        float4 v = ((const float4*)x)[node * 16 + q];
        red4(d_gx + (long long)g * 64 + q * 4, v);
        __half2 h01 = __floats2half2_rn(v.x, v.y);
        __half2 h23 = __floats2half2_rn(v.z, v.w);
        float2 f01 = __half22float2(h01);
        float2 f23 = __half22float2(h23);
        __half2 l01 = __floats2half2_rn(v.x - f01.x, v.y - f01.y);
        __half2 l23 = __floats2half2_rn(v.z - f23.x, v.w - f23.y);
        *(uint2*)(d_xh + node * 64 + q * 4) = make_uint2(*(uint32_t*)&h01, *(uint32_t*)&h23);
        *(uint2*)(d_xl + node * 64 + q * 4) = make_uint2(*(uint32_t*)&l01, *(uint32_t*)&l23);
    }
}

// ---------------- sort pass 2: exclusive scan ----------------
__global__ void k_scan() {
    __shared__ int s[MAXB];
    int t = threadIdx.x;
    int v = d_hist[t];
    s[t] = v;
    __syncthreads();
    for (int o = 1; o < MAXB; o <<= 1) {
        int u = (t >= o) ? s[t - o] : 0;
        __syncthreads();
        s[t] += u;
        __syncthreads();
    }
    d_cur[t] = s[t] - v;
    d_cnt[t] = v;
}

// ---------------- sort pass 3: scatter (block-privatized cursors) ----------------
#define CH 1024
__global__ void k_scatter(const void* __restrict__ ei, const void* __restrict__ bat,
                          long long E) {
    __shared__ int sg_[CH], sr_[CH];
    __shared__ int lh[MAXB], lbase[MAXB];
    int tid = threadIdx.x;
    long long e0 = (long long)blockIdx.x * CH;
    for (int i = tid; i < MAXB; i += 256) lh[i] = 0;
    __syncthreads();
    int e64 = d_f_e64, b64 = d_f_b64;
    for (int i = tid; i < CH; i += 256) {
        long long e = e0 + i;
        if (e < E) {
            int r = (int)ldix(ei, e, e64);
            long long c = ldix(ei, E + e, e64);
            int g = (int)ldix(bat, c, b64);
            sr_[i] = r; sg_[i] = g;
            atomicAdd(&lh[g], 1);
        } else sg_[i] = -1;
    }
    __syncthreads();
    for (int g = tid; g < MAXB; g += 256)
        if (lh[g]) lbase[g] = atomicAdd(&d_cur[g], lh[g]);
    __syncthreads();
    for (int g = tid; g < MAXB; g += 256) lh[g] = 0;
    __syncthreads();
    for (int i = tid; i < CH; i += 256) {
        int g = sg_[i];
        if (g >= 0) {
            int o = atomicAdd(&lh[g], 1);
            d_se[lbase[g] + o] = make_int4(sr_[i], g, (int)(e0 + i), 0);
        }
    }
}

// ---------------- K2: persistent pipelined mma.sync edge kernel ----------------
// Contiguous tile ranges per CTA; lazy cross-tile column accumulation.
__global__ __launch_bounds__(256, 1)
void k_edge(const float* __restrict__ ea, const float* __restrict__ b1a,
            long long E, int ntiles) {
    extern __shared__ char smem[];
    const uint32_t sb = smem_u32(smem);
    const int tid = threadIdx.x, wid = tid >> 5, lane = tid & 31;
    const int wm = wid & 3, wn = wid >> 2;
    const int rowb = wm * 32, colb = wn * 64;

    // contiguous range for this CTA
    const int qn = ntiles / gridDim.x, rn = ntiles % gridDim.x;
    const int start = blockIdx.x * qn + (blockIdx.x < rn ? blockIdx.x : rn);
    const int count = qn + (blockIdx.x < rn ? 1 : 0);

    // one-time: W tile
    {
        const uint4* wsrc = (const uint4*)d_Wt;
        uint4* wdst = (uint4*)(smem + S_W);
        for (int i = tid; i < 2176; i += 256) wdst[i] = wsrc[i];
    }

    float bb0[8], bb1[8];
    #pragma unroll
    for (int ni = 0; ni < 8; ++ni) {
        int colp = colb + ni * 8 + 2 * (lane & 3);
        bb0[ni] = b1a[colp];
        bb1[ni] = b1a[colp + 1];
    }
    const int mycol = tid & 127, myhalf = tid >> 7;
    float qacc = 0.f;
    float acc  = 0.f;        // lazy column-sum accumulator
    int   curG = -1;

    const int eSub = lane >> 4;
    const int c4   = lane & 15;
    const int c4m  = c4 & 7, sel = c4 >> 3;
    const uint32_t xAoff = sel ? 34816u : 0u;
    const __half* xsrc = sel ? d_xl : d_xh;
    const int arow = lane & 15;
    const int akof = (lane >> 4) * 16;
    const int brow = (lane & 7) + ((lane & 16) >> 1);
    const int bkof = ((lane >> 3) & 1) * 16;

    if (count > 0) {
        // ---- prologue: first tile -> buffer A0 ----
        {
            long long e0 = (long long)start * 128;
            if (tid < 128) {
                long long e = e0 + tid;
                int4 v = (e < E) ? d_se[e] : make_int4(0, -1, 0, 0);
                *(int4*)(smem + S_IDX0 + tid * 16) = v;
            }
            __syncthreads();
            #pragma unroll
            for (int i = 0; i < 8; ++i) {
                int e = wid * 16 + i * 2 + eSub;
                int4 iv = *(const int4*)(smem + S_IDX0 + e * 16);
                cpa16(sb + S_A0 + xAoff + (uint32_t)e * 272 + c4m * 16,
                      xsrc + (size_t)iv.x * 64 + c4m * 8);
                cpa16(sb + S_RAW + (uint32_t)e * 272 + c4 * 16,
                      ea + (size_t)iv.z * 64 + c4 * 4);
            }
            asm volatile("cp.async.commit_group;" ::: "memory");
        }

        for (int it = 0; it < count; ++it) {
            const int t = start + it;
            const int p = it & 1;
            const uint32_t sip = (p ? S_IDX1 : S_IDX0);
            const uint32_t sin = (p ? S_IDX0 : S_IDX1);
            const uint32_t sab = (p ? S_A1 : S_A0);
            const uint32_t san = (p ? S_A0 : S_A1);

            asm volatile("cp.async.wait_group 0;" ::: "memory");
            __syncthreads();

            // ---- convert ea raw fp32 -> fp16 hi/lo (cols 64..127 of A) ----
            #pragma unroll
            for (int i = 0; i < 8; ++i) {
                int e = wid * 16 + i * 2 + eSub;
                float4 v = *(const float4*)(smem + S_RAW + (size_t)e * 272 + c4 * 16);
                __half2 h01 = __floats2half2_rn(v.x, v.y);
                __half2 h23 = __floats2half2_rn(v.z, v.w);
                float2 f01 = __half22float2(h01);
                float2 f23 = __half22float2(h23);
                __half2 l01 = __floats2half2_rn(v.x - f01.x, v.y - f01.y);
                __half2 l23 = __floats2half2_rn(v.z - f23.x, v.w - f23.y);
                char* ab = smem + sab + (size_t)e * 272 + 128 + c4 * 8;
                *(uint2*)(ab)          = make_uint2(*(uint32_t*)&h01, *(uint32_t*)&h23);
                *(uint2*)(ab + 34816)  = make_uint2(*(uint32_t*)&l01, *(uint32_t*)&l23);
            }

            // ---- indices for next tile ----
            const bool have_next = (it + 1) < count;
            if (have_next && tid < 128) {
                long long e = (long long)(t + 1) * 128 + tid;
                int4 v = (e < E) ? d_se[e] : make_int4(0, -1, 0, 0);
                *(int4*)(smem + sin + tid * 16) = v;
            }
            __syncthreads();

            // ---- issue cp.async for next tile ----
            if (have_next) {
                #pragma unroll
                for (int i = 0; i < 8; ++i) {
                    int e = wid * 16 + i * 2 + eSub;
                    int4 iv = *(const int4*)(smem + sin + e * 16);
                    cpa16(sb + san + xAoff + (uint32_t)e * 272 + c4m * 16,
                          xsrc + (size_t)iv.x * 64 + c4m * 8);
                    cpa16(sb + S_RAW + (uint32_t)e * 272 + c4 * 16,
                          ea + (size_t)iv.z * 64 + c4 * 4);
                }
                asm volatile("cp.async.commit_group;" ::: "memory");
            }

            // ---- MMA mainloop: 2 products (Ahi+Alo) x Whi ----
            float c[2][8][4];
            #pragma unroll
            for (int mi = 0; mi < 2; ++mi)
                #pragma unroll
                for (int ni = 0; ni < 8; ++ni)
                    #pragma unroll
                    for (int j = 0; j < 4; ++j) c[mi][ni][j] = 0.f;

            #pragma unroll
            for (int kk = 0; kk < 8; ++kk) {
                uint32_t ah[2][4], al_[2][4];
                #pragma unroll
                for (int mi = 0; mi < 2; ++mi) {
                    uint32_t aaddr = sb + sab + (uint32_t)(rowb + mi * 16 + arow) * 272
                                     + kk * 32 + akof;
                    LDSM4(ah[mi], aaddr);
                    LDSM4(al_[mi], aaddr + 34816u);
                }
                #pragma unroll
                for (int np = 0; np < 4; ++np) {
                    uint32_t baddr = sb + S_W + (uint32_t)(colb + np * 16 + brow) * 272
                                     + kk * 32 + bkof;
                    uint32_t bh[4];
                    LDSM4(bh, baddr);
                    #pragma unroll
                    for (int mi = 0; mi < 2; ++mi) {
                        MMA16816(c[mi][np * 2 + 0], ah[mi],  bh[0], bh[1]);
                        MMA16816(c[mi][np * 2 + 1], ah[mi],  bh[2], bh[3]);
                        MMA16816(c[mi][np * 2 + 0], al_[mi], bh[0], bh[1]);
                        MMA16816(c[mi][np * 2 + 1], al_[mi], bh[2], bh[3]);
                    }
                }
            }
            __syncthreads();             // A(t) consumed; sab reusable as dump

            // ---- dump bias+leaky activations to smem (sab as f32 [128][132]) ----
            float* dump = (float*)(smem + sab);
            #pragma unroll
            for (int mi = 0; mi < 2; ++mi) {
                int rA = rowb + mi * 16 + (lane >> 2);
                int rB = rA + 8;
                #pragma unroll
                for (int ni = 0; ni < 8; ++ni) {
                    int colp = colb + ni * 8 + 2 * (lane & 3);
                    float2 vA = make_float2(leaky(c[mi][ni][0] + bb0[ni]),
                                            leaky(c[mi][ni][1] + bb1[ni]));
                    float2 vB = make_float2(leaky(c[mi][ni][2] + bb0[ni]),
                                            leaky(c[mi][ni][3] + bb1[ni]));
                    *(float2*)(dump + rA * 132 + colp) = vA;
                    *(float2*)(dump + rB * 132 + colp) = vB;
                }
            }
            __syncthreads();

            int g0   = *(const int*)(smem + sip + 4);
            int g127 = *(const int*)(smem + sip + 127 * 16 + 4);
            bool mono = (g0 == g127) && (g0 >= 0);

            if (mono) {
                if (g0 != curG) {
                    if (curG >= 0) flush_cols(smem, curG, acc, tid, mycol, myhalf);
                    curG = g0;
                }
                const float* dp = dump + (myhalf * 64) * 132 + mycol;
                float a = 0.f;
                #pragma unroll 8
                for (int e = 0; e < 64; ++e) {
                    float v = dp[e * 132];
                    a += v;
                    qacc += v * v;
                }
                acc += a;
            } else {
                if (curG >= 0) flush_cols(smem, curG, acc, tid, mycol, myhalf);
                curG = -1;
                float a = 0.f;
                int cg = -1;
                const float* dp = dump + (myhalf * 64) * 132 + mycol;
                const char* sgp = smem + sip + (myhalf * 64) * 16 + 4;
                for (int e = 0; e < 64; ++e) {
                    int gg = *(const int*)(sgp + e * 16);
                    float v = dp[e * 132];
                    if (gg != cg) {
                        if (cg >= 0) redf(d_A + (size_t)cg * 128 + mycol, a);
                        a = 0.f;
                        cg = gg;
                    }
                    if (gg >= 0) { a += v; qacc += v * v; }
                }
                if (cg >= 0) redf(d_A + (size_t)cg * 128 + mycol, a);
            }
        }

        if (curG >= 0) flush_cols(smem, curG, acc, tid, mycol, myhalf);
    }

    atomicAdd(&d_Q[mycol], qacc);
}

// ---------------- fused tail: stats -> t2 -> g1 -> g2 -> g3 ----------------
__global__ void k_tail(const float* __restrict__ g1a, const float* __restrict__ be1a,
                       const float* __restrict__ b2a, const float* __restrict__ W2a,
                       const float* __restrict__ W1b, const float* __restrict__ b1b,
                       const float* __restrict__ W2b, const float* __restrict__ b2b,
                       const float* __restrict__ g1b, const float* __restrict__ be1b,
                       const float* __restrict__ W3b, const float* __restrict__ b3b,
                       const float* __restrict__ g2b, const float* __restrict__ be2b,
                       float Ef, float Bf, int B, int ngrid,
                       float* __restrict__ out) {
    __shared__ float sh1[128], sh2[128], sgx[64];
    int blk = blockIdx.x, tid = threadIdx.x;

    if (blk < 128) {
        float s = 0.f;
        for (int b = tid; b < B; b += 128) s += d_A[b * 128 + blk];
        sh1[tid] = s;
        __syncthreads();
        for (int o = 64; o; o >>= 1) {
            if (tid < o) sh1[tid] += sh1[tid + o];
            __syncthreads();
        }
        if (tid == 0) {
            float m = sh1[0] / Ef;
            float v = d_Q[blk] / Ef - m * m;
            float sc = g1a[blk] * rsqrtf(v + EPS);
            d_s1[blk] = sc;
            d_t1[blk] = be1a[blk] - m * sc;
        }
    }
    gbar(0, ngrid);

    if (blk < 128) {
        sh1[tid] = d_t1[tid] * W2a[tid * 128 + blk];
        __syncthreads();
        for (int o = 64; o; o >>= 1) {
            if (tid < o) sh1[tid] += sh1[tid + o];
            __syncthreads();
        }
        if (tid == 0) d_t2[blk] = sh1[0] + b2a[blk];
    }
    gbar(1, ngrid);

    if (blk < B) {
        int b = blk, j = tid;
        sh1[j] = d_A[b * 128 + j] * d_s1[j];
        if (j < 64) sgx[j] = d_gx[b * 64 + j];
        __syncthreads();
        float cf = (float)d_cnt[b];
        float ga = d_t2[j] * cf;
        #pragma unroll 8
        for (int k = 0; k < 128; ++k) ga += sh1[k] * W2a[k * 128 + j];
        sh2[j] = ga;
        __syncthreads();
        float z = b1b[j];
        #pragma unroll 8
        for (int i = 0; i < 64; ++i)  z += sgx[i] * W1b[i * 128 + j];
        #pragma unroll 8
        for (int i = 0; i < 128; ++i) z += sh2[i] * W1b[(64 + i) * 128 + j];
        float a = leaky(z);
        d_a1[b * 128 + j] = a;
        atomicAdd(&d_S1[j], a);
        atomicAdd(&d_Q1[j], a * a);
    }
    gbar(2, ngrid);

    if (blk < B) {
        int b = blk, j = tid;
        float m = d_S1[j] / Bf;
        float v = d_Q1[j] / Bf - m * m;
        float s = g1b[j] * rsqrtf(v + EPS);
        float tt = be1b[j] - m * s;
        sh1[j] = d_a1[b * 128 + j] * s + tt;
        __syncthreads();
        float z = b2b[j];
        #pragma unroll 8
        for (int k = 0; k < 128; ++k) z += sh1[k] * W2b[k * 128 + j];
        float a = leaky(z);
        d_a2[b * 128 + j] = a;
        atomicAdd(&d_S2[j], a);
        atomicAdd(&d_Q2[j], a * a);
        __syncthreads();
    }
    gbar(3, ngrid);

    if (blk < B) {
        int b = blk, j = tid;
        float m = d_S2[j] / Bf;
        float v = d_Q2[j] / Bf - m * m;
        float s = g2b[j] * rsqrtf(v + EPS);
        float tt = be2b[j] - m * s;
        sh1[j] = d_a2[b * 128 + j] * s + tt;
        __syncthreads();
        float z = b3b[j];
        #pragma unroll 8
        for (int k = 0; k < 128; ++k) z += sh1[k] * W3b[k * 128 + j];
        out[b * 128 + j] = z;
    }
}

// ---------------- launch ----------------
extern "C" void kernel_launch(void* const* d_in, const int* in_sizes, int n_in,
                              void* d_out, int out_size) {
    const float* x    = (const float*)d_in[0];
    const void*  ei   = d_in[1];
    const float* ea   = (const float*)d_in[2];
    const void*  bat  = d_in[4];
    const float* W1a  = (const float*)d_in[5];
    const float* b1a  = (const float*)d_in[6];
    const float* g1a  = (const float*)d_in[7];
    const float* be1a = (const float*)d_in[8];
    const float* W2a  = (const float*)d_in[9];
    const float* b2a  = (const float*)d_in[10];
    const float* W1b  = (const float*)d_in[11];
    const float* b1b  = (const float*)d_in[12];
    const float* g1b  = (const float*)d_in[13];
    const float* be1b = (const float*)d_in[14];
    const float* W2b  = (const float*)d_in[15];
    const float* b2b  = (const float*)d_in[16];
    const float* g2b  = (const float*)d_in[17];
    const float* be2b = (const float*)d_in[18];
    const float* W3b  = (const float*)d_in[19];
    const float* b3b  = (const float*)d_in[20];

    long long N = (long long)in_sizes[0] / 64;
    long long E = (long long)in_sizes[2] / 64;
    int B = in_sizes[3];
    if (B > MAXB) B = MAXB;

    static int smem_set = 0;
    if (!smem_set) {
        cudaFuncSetAttribute(k_edge, cudaFuncAttributeMaxDynamicSharedMemorySize, SMEM_TOT);
        smem_set = 1;
    }

    k_zero<<<256, 256>>>(ei, bat, 2 * E, N);

    int gridP = (int)((N * 16 + 255) / 256);
    if (gridP < 256) gridP = 256;
    k_pre<<<gridP, 256>>>(W1a, ei, bat, x, E, N);

    k_scan<<<1, MAXB>>>();
    int gridS = (int)((E + CH - 1) / CH);
    k_scatter<<<gridS, 256>>>(ei, bat, E);

    int ntiles = (int)((E + 127) / 128);
    int grid = ntiles < 148 ? ntiles : 148;
    k_edge<<<grid, 256, SMEM_TOT>>>(ea, b1a, E, ntiles);

    int ng = B > 128 ? B : 128;
    k_tail<<<ng, 128>>>(g1a, be1a, b2a, W2a, W1b, b1b, W2b, b2b, g1b, be1b,
                        W3b, b3b, g2b, be2b, (float)E, (float)B, B, ng,
                        (float*)d_out);
}

// round 17
// speedup vs baseline: 1.3511x; 1.0904x over previous
#include <cuda_runtime.h>
#include <cuda_fp16.h>
#include <cstdint>

#define MAXB  1024
#define EMAX  (1 << 20)
#define NMAX  65536
#define EPS   1e-5f
#define SLOPE 0.01f

// ---------------- static device scratch (no allocations allowed) ----------------
__device__ __align__(16) float d_A [MAXB * 128];
__device__ __align__(16) float d_gx[MAXB * 64];
__device__            int   d_cnt[MAXB];
__device__ __align__(16) float d_Q [128];
__device__ __align__(16) float d_s1[128], d_t1[128], d_t2[128];
__device__ __align__(16) float d_S1[128], d_Q1[128], d_S2[128], d_Q2[128];
__device__ __align__(16) float d_a1[MAXB * 128], d_a2[MAXB * 128];
__device__ __align__(16) unsigned short d_Wt[17408];  // W^T fp16 hi [128][136]
__device__ __align__(16) __half d_xh[NMAX * 64];      // x fp16 hi
__device__ __align__(16) __half d_xl[NMAX * 64];      // x fp16 lo
__device__ __align__(16) int4  d_se[EMAX];            // sorted edges {row, g, e_orig, 0}
__device__            int   d_hist[MAXB], d_cur[MAXB];
__device__            int   d_bar[8];
__device__            int   d_f_e64, d_f_b64;

// ---------------- smem layout of k_edge ----------------
#define S_IDX0  0            // int4 {row,g,eorig,0} x 128
#define S_IDX1  2048
#define S_CB    4096         // 2KB fold buffers
#define S_W     6144         // Whi [128][272B] = 34816
#define S_A0    40960        // tile buffer 0: Ahi|Alo (69632); reused as f32 dump
#define S_A1    110592       // tile buffer 1
#define S_RAW   180224       // raw fp32 ea [128][272B] = 34816
#define SMEM_TOT 215040

// ---------------- helpers ----------------
__device__ __forceinline__ void red4(float* p, float4 v) {
    asm volatile("red.global.add.v4.f32 [%0], {%1,%2,%3,%4};"
                 :: "l"(p), "f"(v.x), "f"(v.y), "f"(v.z), "f"(v.w) : "memory");
}
__device__ __forceinline__ void redf(float* p, float v) {
    asm volatile("red.global.add.f32 [%0], %1;" :: "l"(p), "f"(v) : "memory");
}
__device__ __forceinline__ long long ldix(const void* p, long long i, int is64) {
    return is64 ? ((const long long*)p)[i] : (long long)((const int*)p)[i];
}
__device__ __forceinline__ float leaky(float z) { return z >= 0.f ? z : SLOPE * z; }
__device__ __forceinline__ uint32_t smem_u32(const void* p) {
    uint32_t a;
    asm("{ .reg .u64 t; cvta.to.shared.u64 t, %1; cvt.u32.u64 %0, t; }" : "=r"(a) : "l"(p));
    return a;
}
__device__ __forceinline__ void cpa16(uint32_t s, const void* g) {
    asm volatile("cp.async.cg.shared.global [%0], [%1], 16;" :: "r"(s), "l"(g) : "memory");
}
#define LDSM4(r, a) \
    asm volatile("ldmatrix.sync.aligned.m8n8.x4.shared.b16 {%0,%1,%2,%3}, [%4];" \
        : "=r"((r)[0]), "=r"((r)[1]), "=r"((r)[2]), "=r"((r)[3]) : "r"(a))
#define MMA16816(c, a, b0, b1) \
    asm volatile("mma.sync.aligned.m16n8k16.row.col.f32.f16.f16.f32 " \
        "{%0,%1,%2,%3}, {%4,%5,%6,%7}, {%8,%9}, {%0,%1,%2,%3};" \
        : "+f"((c)[0]), "+f"((c)[1]), "+f"((c)[2]), "+f"((c)[3]) \
        : "r"((a)[0]), "r"((a)[1]), "r"((a)[2]), "r"((a)[3]), "r"(b0), "r"(b1))

__device__ __forceinline__ void gbar(int i, int n) {
    __syncthreads();
    if (threadIdx.x == 0) {
        __threadfence();
        atomicAdd(&d_bar[i], 1);
        while (atomicAdd(&d_bar[i], 0) < n) { __nanosleep(64); }
    }
    __syncthreads();
}

// ---------------- K0: zero scratch + detect index width ----------------
__global__ void k_zero(const void* eidx, const void* bat,
                       long long e2w, long long nw) {
    int idx = blockIdx.x * blockDim.x + threadIdx.x;
    int stride = gridDim.x * blockDim.x;
    for (int i = idx; i < MAXB * 128; i += stride) d_A[i] = 0.f;
    for (int i = idx; i < MAXB * 64;  i += stride) d_gx[i] = 0.f;
    for (int i = idx; i < MAXB;       i += stride) d_hist[i] = 0;
    for (int i = idx; i < 128;        i += stride) {
        d_Q[i] = 0.f; d_S1[i] = 0.f; d_Q1[i] = 0.f; d_S2[i] = 0.f; d_Q2[i] = 0.f;
    }
    if (idx < 8) d_bar[idx] = 0;
    if (blockIdx.x == 0 && threadIdx.x < 32) {
        const unsigned* we = (const unsigned*)eidx;
        const unsigned* wb = (const unsigned*)bat;
        int lane = threadIdx.x;
        int nz_e = 0, nz_b = 0;
        long long se = e2w / 64; if (se < 2) se = 2;
        long long sb = nw  / 64; if (sb < 2) sb = 2;
        for (int s = 0; s < 2; ++s) {
            long long k = lane * 2 + s;
            long long pe = (k * se) | 1; if (pe >= e2w) pe = 1;
            long long pb = (k * sb) | 1; if (pb >= nw)  pb = 1;
            if (we[pe] != 0u) nz_e++;
            if (wb[pb] != 0u) nz_b++;
        }
        for (int o = 16; o > 0; o >>= 1) {
            nz_e += __shfl_xor_sync(0xffffffffu, nz_e, o);
            nz_b += __shfl_xor_sync(0xffffffffu, nz_b, o);
        }
        if (lane == 0) {
            d_f_e64 = (nz_e < 8) ? 1 : 0;
            d_f_b64 = (nz_b < 8) ? 1 : 0;
        }
    }
}

// ---------------- K1a: histogram over graphs (side stream) ----------------
__global__ void k_hist(const void* __restrict__ ei, const void* __restrict__ bat,
                       long long E) {
    __shared__ int lh[MAXB];
    int tid = threadIdx.x;
    for (int i = tid; i < MAXB; i += 256) lh[i] = 0;
    __syncthreads();
    int e64 = d_f_e64, b64 = d_f_b64;
    long long stride = (long long)gridDim.x * 256;
    for (long long e = (long long)blockIdx.x * 256 + tid; e < E; e += stride) {
        long long c = ldix(ei, E + e, e64);
        atomicAdd(&lh[(int)ldix(bat, c, b64)], 1);
    }
    __syncthreads();
    for (int i = tid; i < MAXB; i += 256)
        if (lh[i]) atomicAdd(&d_hist[i], lh[i]);
}

// ---------------- K1b: wprep + gx + x->fp16 (main stream) ----------------
__global__ void k_pre(const float* __restrict__ W1a, const void* __restrict__ bat,
                      const float* __restrict__ x, long long N) {
    int tid = threadIdx.x, bid = blockIdx.x;
    long long gtid = (long long)bid * 256 + tid;
    int b64 = d_f_b64;

    if (gtid < 16384) {
        int k = (int)(gtid >> 7), n = (int)(gtid & 127);
        __half h = __float2half(W1a[k * 128 + n]);
        d_Wt[n * 136 + k] = *(unsigned short*)&h;
    }

    long long tot = N * 16;
    long long gstride = (long long)gridDim.x * 256;
    for (long long idx = gtid; idx < tot; idx += gstride) {
        long long node = idx >> 4;
        int q = (int)(idx & 15);
        int g = (int)ldix(bat, node, b64);
        float4 v = ((const float4*)x)[node * 16 + q];
        red4(d_gx + (long long)g * 64 + q * 4, v);
        __half2 h01 = __floats2half2_rn(v.x, v.y);
        __half2 h23 = __floats2half2_rn(v.z, v.w);
        float2 f01 = __half22float2(h01);
        float2 f23 = __half22float2(h23);
        __half2 l01 = __floats2half2_rn(v.x - f01.x, v.y - f01.y);
        __half2 l23 = __floats2half2_rn(v.z - f23.x, v.w - f23.y);
        *(uint2*)(d_xh + node * 64 + q * 4) = make_uint2(*(uint32_t*)&h01, *(uint32_t*)&h23);
        *(uint2*)(d_xl + node * 64 + q * 4) = make_uint2(*(uint32_t*)&l01, *(uint32_t*)&l23);
    }
}

// ---------------- sort pass 2: exclusive scan ----------------
__global__ void k_scan() {
    __shared__ int s[MAXB];
    int t = threadIdx.x;
    int v = d_hist[t];
    s[t] = v;
    __syncthreads();
    for (int o = 1; o < MAXB; o <<= 1) {
        int u = (t >= o) ? s[t - o] : 0;
        __syncthreads();
        s[t] += u;
        __syncthreads();
    }
    d_cur[t] = s[t] - v;
    d_cnt[t] = v;
}

// ---------------- sort pass 3: scatter (block-privatized cursors) ----------------
#define CH 1024
__global__ void k_scatter(const void* __restrict__ ei, const void* __restrict__ bat,
                          long long E) {
    __shared__ int sg_[CH], sr_[CH];
    __shared__ int lh[MAXB], lbase[MAXB];
    int tid = threadIdx.x;
    long long e0 = (long long)blockIdx.x * CH;
    for (int i = tid; i < MAXB; i += 256) lh[i] = 0;
    __syncthreads();
    int e64 = d_f_e64, b64 = d_f_b64;
    for (int i = tid; i < CH; i += 256) {
        long long e = e0 + i;
        if (e < E) {
            int r = (int)ldix(ei, e, e64);
            long long c = ldix(ei, E + e, e64);
            int g = (int)ldix(bat, c, b64);
            sr_[i] = r; sg_[i] = g;
            atomicAdd(&lh[g], 1);
        } else sg_[i] = -1;
    }
    __syncthreads();
    for (int g = tid; g < MAXB; g += 256)
        if (lh[g]) lbase[g] = atomicAdd(&d_cur[g], lh[g]);
    __syncthreads();
    for (int g = tid; g < MAXB; g += 256) lh[g] = 0;
    __syncthreads();
    for (int i = tid; i < CH; i += 256) {
        int g = sg_[i];
        if (g >= 0) {
            int o = atomicAdd(&lh[g], 1);
            d_se[lbase[g] + o] = make_int4(sr_[i], g, (int)(e0 + i), 0);
        }
    }
}

// ---------------- K2: persistent pipelined mma.sync edge kernel ----------------
// Contiguous tile ranges; mono tiles accumulate in fragment registers.
__global__ __launch_bounds__(256, 1)
void k_edge(const float* __restrict__ ea, const float* __restrict__ b1a,
            long long E, int ntiles) {
    extern __shared__ char smem[];
    const uint32_t sb = smem_u32(smem);
    const int tid = threadIdx.x, wid = tid >> 5, lane = tid & 31;
    const int wm = wid & 3, wn = wid >> 2;
    const int rowb = wm * 32, colb = wn * 64;

    const int qn = ntiles / gridDim.x, rn = ntiles % gridDim.x;
    const int start = blockIdx.x * qn + (blockIdx.x < rn ? blockIdx.x : rn);
    const int count = qn + (blockIdx.x < rn ? 1 : 0);

    {
        const uint4* wsrc = (const uint4*)d_Wt;
        uint4* wdst = (uint4*)(smem + S_W);
        for (int i = tid; i < 2176; i += 256) wdst[i] = wsrc[i];
    }

    float bb0[8], bb1[8];
    #pragma unroll
    for (int ni = 0; ni < 8; ++ni) {
        int colp = colb + ni * 8 + 2 * (lane & 3);
        bb0[ni] = b1a[colp];
        bb1[ni] = b1a[colp + 1];
    }
    const int mycol = tid & 127, myhalf = tid >> 7;
    float qacc = 0.f;                       // boundary-path Q
    float acc0[8], acc1[8], q0[8], q1[8];   // fragment-layout accumulators
    #pragma unroll
    for (int ni = 0; ni < 8; ++ni) { acc0[ni] = 0.f; acc1[ni] = 0.f; q0[ni] = 0.f; q1[ni] = 0.f; }
    int curG = -1;

    const int eSub = lane >> 4;
    const int c4   = lane & 15;
    const int c4m  = c4 & 7, sel = c4 >> 3;
    const uint32_t xAoff = sel ? 34816u : 0u;
    const __half* xsrc = sel ? d_xl : d_xh;
    const int arow = lane & 15;
    const int akof = (lane >> 4) * 16;
    const int brow = (lane & 7) + ((lane & 16) >> 1);
    const int bkof = ((lane >> 3) & 1) * 16;

    // flush fragment accumulators for graph g (all threads)
    auto flush_frag = [&](int g) {
        float* cb  = (float*)(smem + S_CB);        // [4][128]
        float* cb2 = (float*)(smem + S_CB + 2048 - 512);
        __syncthreads();
        #pragma unroll
        for (int ni = 0; ni < 8; ++ni) {
            float s0 = acc0[ni], s1 = acc1[ni];
            #pragma unroll
            for (int o = 4; o < 32; o <<= 1) {
                s0 += __shfl_xor_sync(0xffffffffu, s0, o);
                s1 += __shfl_xor_sync(0xffffffffu, s1, o);
            }
            if (lane < 4) {
                int col = colb + ni * 8 + lane * 2;
                *(float2*)(cb + wm * 128 + col) = make_float2(s0, s1);
            }
            acc0[ni] = 0.f; acc1[ni] = 0.f;
        }
        __syncthreads();
        if (tid < 128)
            cb2[tid] = cb[tid] + cb[128 + tid] + cb[256 + tid] + cb[384 + tid];
        __syncthreads();
        if (tid < 32) {
            float4 vv = *(const float4*)(cb2 + tid * 4);
            red4(d_A + (size_t)g * 128 + tid * 4, vv);
        }
    };

    if (count > 0) {
        {
            long long e0 = (long long)start * 128;
            if (tid < 128) {
                long long e = e0 + tid;
                int4 v = (e < E) ? d_se[e] : make_int4(0, -1, 0, 0);
                *(int4*)(smem + S_IDX0 + tid * 16) = v;
            }
            __syncthreads();
            #pragma unroll
            for (int i = 0; i < 8; ++i) {
                int e = wid * 16 + i * 2 + eSub;
                int4 iv = *(const int4*)(smem + S_IDX0 + e * 16);
                cpa16(sb + S_A0 + xAoff + (uint32_t)e * 272 + c4m * 16,
                      xsrc + (size_t)iv.x * 64 + c4m * 8);
                cpa16(sb + S_RAW + (uint32_t)e * 272 + c4 * 16,
                      ea + (size_t)iv.z * 64 + c4 * 4);
            }
            asm volatile("cp.async.commit_group;" ::: "memory");
        }

        for (int it = 0; it < count; ++it) {
            const int t = start + it;
            const int p = it & 1;
            const uint32_t sip = (p ? S_IDX1 : S_IDX0);
            const uint32_t sin = (p ? S_IDX0 : S_IDX1);
            const uint32_t sab = (p ? S_A1 : S_A0);
            const uint32_t san = (p ? S_A0 : S_A1);

            asm volatile("cp.async.wait_group 0;" ::: "memory");
            __syncthreads();

            // ---- convert ea raw fp32 -> fp16 hi/lo (cols 64..127 of A) ----
            #pragma unroll
            for (int i = 0; i < 8; ++i) {
                int e = wid * 16 + i * 2 + eSub;
                float4 v = *(const float4*)(smem + S_RAW + (size_t)e * 272 + c4 * 16);
                __half2 h01 = __floats2half2_rn(v.x, v.y);
                __half2 h23 = __floats2half2_rn(v.z, v.w);
                float2 f01 = __half22float2(h01);
                float2 f23 = __half22float2(h23);
                __half2 l01 = __floats2half2_rn(v.x - f01.x, v.y - f01.y);
                __half2 l23 = __floats2half2_rn(v.z - f23.x, v.w - f23.y);
                char* ab = smem + sab + (size_t)e * 272 + 128 + c4 * 8;
                *(uint2*)(ab)          = make_uint2(*(uint32_t*)&h01, *(uint32_t*)&h23);
                *(uint2*)(ab + 34816)  = make_uint2(*(uint32_t*)&l01, *(uint32_t*)&l23);
            }

            const bool have_next = (it + 1) < count;
            if (have_next && tid < 128) {
                long long e = (long long)(t + 1) * 128 + tid;
                int4 v = (e < E) ? d_se[e] : make_int4(0, -1, 0, 0);
                *(int4*)(smem + sin + tid * 16) = v;
            }
            __syncthreads();

            if (have_next) {
                #pragma unroll
                for (int i = 0; i < 8; ++i) {
                    int e = wid * 16 + i * 2 + eSub;
                    int4 iv = *(const int4*)(smem + sin + e * 16);
                    cpa16(sb + san + xAoff + (uint32_t)e * 272 + c4m * 16,
                          xsrc + (size_t)iv.x * 64 + c4m * 8);
                    cpa16(sb + S_RAW + (uint32_t)e * 272 + c4 * 16,
                          ea + (size_t)iv.z * 64 + c4 * 4);
                }
                asm volatile("cp.async.commit_group;" ::: "memory");
            }

            // ---- MMA mainloop ----
            float c[2][8][4];
            #pragma unroll
            for (int mi = 0; mi < 2; ++mi)
                #pragma unroll
                for (int ni = 0; ni < 8; ++ni)
                    #pragma unroll
                    for (int j = 0; j < 4; ++j) c[mi][ni][j] = 0.f;

            #pragma unroll
            for (int kk = 0; kk < 8; ++kk) {
                uint32_t ah[2][4], al_[2][4];
                #pragma unroll
                for (int mi = 0; mi < 2; ++mi) {
                    uint32_t aaddr = sb + sab + (uint32_t)(rowb + mi * 16 + arow) * 272
                                     + kk * 32 + akof;
                    LDSM4(ah[mi], aaddr);
                    LDSM4(al_[mi], aaddr + 34816u);
                }
                #pragma unroll
                for (int np = 0; np < 4; ++np) {
                    uint32_t baddr = sb + S_W + (uint32_t)(colb + np * 16 + brow) * 272
                                     + kk * 32 + bkof;
                    uint32_t bh[4];
                    LDSM4(bh, baddr);
                    #pragma unroll
                    for (int mi = 0; mi < 2; ++mi) {
                        MMA16816(c[mi][np * 2 + 0], ah[mi],  bh[0], bh[1]);
                        MMA16816(c[mi][np * 2 + 1], ah[mi],  bh[2], bh[3]);
                        MMA16816(c[mi][np * 2 + 0], al_[mi], bh[0], bh[1]);
                        MMA16816(c[mi][np * 2 + 1], al_[mi], bh[2], bh[3]);
                    }
                }
            }

            int g0   = *(const int*)(smem + sip + 4);
            int g127 = *(const int*)(smem + sip + 127 * 16 + 4);
            bool mono = (g0 == g127) && (g0 >= 0);

            if (mono) {
                if (g0 != curG) {
                    if (curG >= 0) flush_frag(curG);
                    curG = g0;
                }
                // pure register accumulation — no syncs, no smem
                #pragma unroll
                for (int ni = 0; ni < 8; ++ni) {
                    float a0 = leaky(c[0][ni][0] + bb0[ni]);
                    float a1 = leaky(c[0][ni][1] + bb1[ni]);
                    float a2 = leaky(c[0][ni][2] + bb0[ni]);
                    float a3 = leaky(c[0][ni][3] + bb1[ni]);
                    float a4 = leaky(c[1][ni][0] + bb0[ni]);
                    float a5 = leaky(c[1][ni][1] + bb1[ni]);
                    float a6 = leaky(c[1][ni][2] + bb0[ni]);
                    float a7 = leaky(c[1][ni][3] + bb1[ni]);
                    acc0[ni] += (a0 + a2) + (a4 + a6);
                    acc1[ni] += (a1 + a3) + (a5 + a7);
                    q0[ni] += (a0 * a0 + a2 * a2) + (a4 * a4 + a6 * a6);
                    q1[ni] += (a1 * a1 + a3 * a3) + (a5 * a5 + a7 * a7);
                }
            } else {
                if (curG >= 0) flush_frag(curG);
                curG = -1;
                __syncthreads();         // LDSM reads of sab done before dump reuse
                float* dump = (float*)(smem + sab);
                #pragma unroll
                for (int mi = 0; mi < 2; ++mi) {
                    int rA = rowb + mi * 16 + (lane >> 2);
                    int rB = rA + 8;
                    #pragma unroll
                    for (int ni = 0; ni < 8; ++ni) {
                        int colp = colb + ni * 8 + 2 * (lane & 3);
                        float2 vA = make_float2(leaky(c[mi][ni][0] + bb0[ni]),
                                                leaky(c[mi][ni][1] + bb1[ni]));
                        float2 vB = make_float2(leaky(c[mi][ni][2] + bb0[ni]),
                                                leaky(c[mi][ni][3] + bb1[ni]));
                        *(float2*)(dump + rA * 132 + colp) = vA;
                        *(float2*)(dump + rB * 132 + colp) = vB;
                    }
                }
                __syncthreads();
                float a = 0.f;
                int cg = -1;
                const float* dp = dump + (myhalf * 64) * 132 + mycol;
                const char* sgp = smem + sip + (myhalf * 64) * 16 + 4;
                for (int e = 0; e < 64; ++e) {
                    int gg = *(const int*)(sgp + e * 16);
                    float v = dp[e * 132];
                    if (gg != cg) {
                        if (cg >= 0) redf(d_A + (size_t)cg * 128 + mycol, a);
                        a = 0.f;
                        cg = gg;
                    }
                    if (gg >= 0) { a += v; qacc += v * v; }
                }
                if (cg >= 0) redf(d_A + (size_t)cg * 128 + mycol, a);
                __syncthreads();         // dump reads done before next-tile reuse
            }
        }

        if (curG >= 0) flush_frag(curG);
    }

    // ---- flush Q: fragment part + scalar boundary part ----
    #pragma unroll
    for (int ni = 0; ni < 8; ++ni) {
        #pragma unroll
        for (int o = 4; o < 32; o <<= 1) {
            q0[ni] += __shfl_xor_sync(0xffffffffu, q0[ni], o);
            q1[ni] += __shfl_xor_sync(0xffffffffu, q1[ni], o);
        }
    }
    if (lane < 4) {
        #pragma unroll
        for (int ni = 0; ni < 8; ++ni) {
            int colp = colb + ni * 8 + lane * 2;
            atomicAdd(&d_Q[colp],     q0[ni]);
            atomicAdd(&d_Q[colp + 1], q1[ni]);
        }
    }
    atomicAdd(&d_Q[mycol], qacc);
}

// ---------------- fused tail: stats -> t2 -> g1 -> g2 -> g3 ----------------
__global__ void k_tail(const float* __restrict__ g1a, const float* __restrict__ be1a,
                       const float* __restrict__ b2a, const float* __restrict__ W2a,
                       const float* __restrict__ W1b, const float* __restrict__ b1b,
                       const float* __restrict__ W2b, const float* __restrict__ b2b,
                       const float* __restrict__ g1b, const float* __restrict__ be1b,
                       const float* __restrict__ W3b, const float* __restrict__ b3b,
                       const float* __restrict__ g2b, const float* __restrict__ be2b,
                       float Ef, float Bf, int B, int ngrid,
                       float* __restrict__ out) {
    __shared__ float sh1[128], sh2[128], sgx[64];
    int blk = blockIdx.x, tid = threadIdx.x;

    if (blk < 128) {
        float s = 0.f;
        for (int b = tid; b < B; b += 128) s += d_A[b * 128 + blk];
        sh1[tid] = s;
        __syncthreads();
        for (int o = 64; o; o >>= 1) {
            if (tid < o) sh1[tid] += sh1[tid + o];
            __syncthreads();
        }
        if (tid == 0) {
            float m = sh1[0] / Ef;
            float v = d_Q[blk] / Ef - m * m;
            float sc = g1a[blk] * rsqrtf(v + EPS);
            d_s1[blk] = sc;
            d_t1[blk] = be1a[blk] - m * sc;
        }
    }
    gbar(0, ngrid);

    if (blk < 128) {
        sh1[tid] = d_t1[tid] * W2a[tid * 128 + blk];
        __syncthreads();
        for (int o = 64; o; o >>= 1) {
            if (tid < o) sh1[tid] += sh1[tid + o];
            __syncthreads();
        }
        if (tid == 0) d_t2[blk] = sh1[0] + b2a[blk];
    }
    gbar(1, ngrid);

    if (blk < B) {
        int b = blk, j = tid;
        sh1[j] = d_A[b * 128 + j] * d_s1[j];
        if (j < 64) sgx[j] = d_gx[b * 64 + j];
        __syncthreads();
        float cf = (float)d_cnt[b];
        float ga = d_t2[j] * cf;
        #pragma unroll 8
        for (int k = 0; k < 128; ++k) ga += sh1[k] * W2a[k * 128 + j];
        sh2[j] = ga;
        __syncthreads();
        float z = b1b[j];
        #pragma unroll 8
        for (int i = 0; i < 64; ++i)  z += sgx[i] * W1b[i * 128 + j];
        #pragma unroll 8
        for (int i = 0; i < 128; ++i) z += sh2[i] * W1b[(64 + i) * 128 + j];
        float a = leaky(z);
        d_a1[b * 128 + j] = a;
        atomicAdd(&d_S1[j], a);
        atomicAdd(&d_Q1[j], a * a);
    }
    gbar(2, ngrid);

    if (blk < B) {
        int b = blk, j = tid;
        float m = d_S1[j] / Bf;
        float v = d_Q1[j] / Bf - m * m;
        float s = g1b[j] * rsqrtf(v + EPS);
        float tt = be1b[j] - m * s;
        sh1[j] = d_a1[b * 128 + j] * s + tt;
        __syncthreads();
        float z = b2b[j];
        #pragma unroll 8
        for (int k = 0; k < 128; ++k) z += sh1[k] * W2b[k * 128 + j];
        float a = leaky(z);
        d_a2[b * 128 + j] = a;
        atomicAdd(&d_S2[j], a);
        atomicAdd(&d_Q2[j], a * a);
        __syncthreads();
    }
    gbar(3, ngrid);

    if (blk < B) {
        int b = blk, j = tid;
        float m = d_S2[j] / Bf;
        float v = d_Q2[j] / Bf - m * m;
        float s = g2b[j] * rsqrtf(v + EPS);
        float tt = be2b[j] - m * s;
        sh1[j] = d_a2[b * 128 + j] * s + tt;
        __syncthreads();
        float z = b3b[j];
        #pragma unroll 8
        for (int k = 0; k < 128; ++k) z += sh1[k] * W3b[k * 128 + j];
        out[b * 128 + j] = z;
    }
}

// ---------------- launch ----------------
extern "C" void kernel_launch(void* const* d_in, const int* in_sizes, int n_in,
                              void* d_out, int out_size) {
    const float* x    = (const float*)d_in[0];
    const void*  ei   = d_in[1];
    const float* ea   = (const float*)d_in[2];
    const void*  bat  = d_in[4];
    const float* W1a  = (const float*)d_in[5];
    const float* b1a  = (const float*)d_in[6];
    const float* g1a  = (const float*)d_in[7];
    const float* be1a = (const float*)d_in[8];
    const float* W2a  = (const float*)d_in[9];
    const float* b2a  = (const float*)d_in[10];
    const float* W1b  = (const float*)d_in[11];
    const float* b1b  = (const float*)d_in[12];
    const float* g1b  = (const float*)d_in[13];
    const float* be1b = (const float*)d_in[14];
    const float* W2b  = (const float*)d_in[15];
    const float* b2b  = (const float*)d_in[16];
    const float* g2b  = (const float*)d_in[17];
    const float* be2b = (const float*)d_in[18];
    const float* W3b  = (const float*)d_in[19];
    const float* b3b  = (const float*)d_in[20];

    long long N = (long long)in_sizes[0] / 64;
    long long E = (long long)in_sizes[2] / 64;
    int B = in_sizes[3];
    if (B > MAXB) B = MAXB;

    static int inited = 0;
    static cudaStream_t s2;
    static cudaEvent_t evFork, evJoin;
    if (!inited) {
        cudaFuncSetAttribute(k_edge, cudaFuncAttributeMaxDynamicSharedMemorySize, SMEM_TOT);
        cudaStreamCreateWithFlags(&s2, cudaStreamNonBlocking);
        cudaEventCreateWithFlags(&evFork, cudaEventDisableTiming);
        cudaEventCreateWithFlags(&evJoin, cudaEventDisableTiming);
        inited = 1;
    }

    k_zero<<<256, 256>>>(ei, bat, 2 * E, N);

    // fork: sort chain on s2, x-side work on main stream
    cudaEventRecord(evFork, 0);
    cudaStreamWaitEvent(s2, evFork, 0);
    k_hist<<<256, 256, 0, s2>>>(ei, bat, E);
    k_scan<<<1, MAXB, 0, s2>>>();
    int gridS = (int)((E + CH - 1) / CH);
    k_scatter<<<gridS, 256, 0, s2>>>(ei, bat, E);
    cudaEventRecord(evJoin, s2);

    int gridP = (int)((N * 16 + 255) / 256);
    if (gridP < 256) gridP = 256;
    k_pre<<<gridP, 256>>>(W1a, bat, x, N);

    cudaStreamWaitEvent(0, evJoin, 0);

    int ntiles = (int)((E + 127) / 128);
    int grid = ntiles < 148 ? ntiles : 148;
    k_edge<<<grid, 256, SMEM_TOT>>>(ea, b1a, E, ntiles);

    int ng = B > 128 ? B : 128;
    k_tail<<<ng, 128>>>(g1a, be1a, b2a, W2a, W1b, b1b, W2b, b2b, g1b, be1b,
                        W3b, b3b, g2b, be2b, (float)E, (float)B, B, ng,
                        (float*)d_out);
}